// round 14
// baseline (speedup 1.0000x reference)
#include <cuda_runtime.h>
#include <cuda_bf16.h>
#include <math.h>
#include <stdint.h>

// Problem constants
#define NTOK  4096      // B*T
#define TSEQ  2048
#define EMBED 1024
#define NH    16
#define HDIM  64

// ---------------------------------------------------------------------------
// Scratch (device globals: allocation-free per harness rules)
// ---------------------------------------------------------------------------
__device__ __nv_bfloat16 g_xhi[(size_t)NTOK * EMBED];
__device__ __nv_bfloat16 g_xlo[(size_t)NTOK * EMBED];
__device__ __nv_bfloat16 g_Qh[(size_t)NTOK * EMBED];
__device__ __nv_bfloat16 g_Ql[(size_t)NTOK * EMBED];
__device__ __nv_bfloat16 g_Kh[(size_t)NTOK * EMBED];
__device__ __nv_bfloat16 g_Kl[(size_t)NTOK * EMBED];
__device__ __nv_bfloat16 g_Vh[(size_t)NTOK * EMBED];
__device__ __nv_bfloat16 g_Vl[(size_t)NTOK * EMBED];
__device__ __nv_bfloat16 g_ahi[(size_t)NTOK * EMBED];
__device__ __nv_bfloat16 g_alo[(size_t)NTOK * EMBED];
__device__ __nv_bfloat16 g_whi[(size_t)4 * EMBED * EMBED];  // Wq^T,Wk^T,Wv^T,Wo^T
__device__ __nv_bfloat16 g_wlo[(size_t)4 * EMBED * EMBED];

// ---------------------------------------------------------------------------
// PTX helpers (compute_103-safe: ldmatrix + mma.sync + cp.async)
// ---------------------------------------------------------------------------
__device__ __forceinline__ uint32_t smem_u32(const void* p) {
    uint32_t a;
    asm("{ .reg .u64 t; cvta.to.shared.u64 t, %1; cvt.u32.u64 %0, t; }"
        : "=r"(a) : "l"(p));
    return a;
}

__device__ __forceinline__ void cp16(uint32_t dst, const void* src) {
    asm volatile("cp.async.cg.shared.global [%0], [%1], 16;"
                 :: "r"(dst), "l"(src));
}
#define CP_COMMIT() asm volatile("cp.async.commit_group;" ::: "memory")
#define CP_WAIT0()  asm volatile("cp.async.wait_group 0;" ::: "memory")
#define CP_WAIT1()  asm volatile("cp.async.wait_group 1;" ::: "memory")

__device__ __forceinline__ void ldsm_x4(uint32_t addr, uint32_t& r0, uint32_t& r1,
                                        uint32_t& r2, uint32_t& r3) {
    asm volatile("ldmatrix.sync.aligned.m8n8.x4.shared.b16 {%0,%1,%2,%3}, [%4];"
                 : "=r"(r0), "=r"(r1), "=r"(r2), "=r"(r3) : "r"(addr));
}

__device__ __forceinline__ void ldsm_x4_t(uint32_t addr, uint32_t& r0, uint32_t& r1,
                                          uint32_t& r2, uint32_t& r3) {
    asm volatile("ldmatrix.sync.aligned.m8n8.x4.trans.shared.b16 {%0,%1,%2,%3}, [%4];"
                 : "=r"(r0), "=r"(r1), "=r"(r2), "=r"(r3) : "r"(addr));
}

__device__ __forceinline__ void mma16816(float* d, const uint32_t* a,
                                         const uint32_t* b) {
    asm volatile(
        "mma.sync.aligned.m16n8k16.row.col.f32.bf16.bf16.f32 "
        "{%0,%1,%2,%3}, {%4,%5,%6,%7}, {%8,%9}, {%0,%1,%2,%3};"
        : "+f"(d[0]), "+f"(d[1]), "+f"(d[2]), "+f"(d[3])
        : "r"(a[0]), "r"(a[1]), "r"(a[2]), "r"(a[3]), "r"(b[0]), "r"(b[1]));
}

// fp32 -> (bf16 hi, bf16 lo) split
__device__ __forceinline__ void split_bf16(float v, __nv_bfloat16& h, __nv_bfloat16& l) {
    h = __float2bfloat16(v);
    l = __float2bfloat16(v - __bfloat162float(h));
}

__device__ __forceinline__ void split2(float a, float b, uint32_t& hi, uint32_t& lo) {
    __nv_bfloat16 ha = __float2bfloat16(a);
    __nv_bfloat16 hb = __float2bfloat16(b);
    __nv_bfloat162 hp = __halves2bfloat162(ha, hb);
    hi = *reinterpret_cast<uint32_t*>(&hp);
    __nv_bfloat162 lp = __floats2bfloat162_rn(a - __bfloat162float(ha),
                                              b - __bfloat162float(hb));
    lo = *reinterpret_cast<uint32_t*>(&lp);
}

// Software exp2 on the FMA pipe (no MUFU). rel err ~2e-6.
__device__ __forceinline__ float fexp2(float x) {
    x = fmaxf(x, -125.0f);
    float t = __fadd_rn(x, 12582912.0f);
    int   k = __float_as_int(t) - 0x4B400000;
    float f = __fsub_rn(x, __fsub_rn(t, 12582912.0f));
    float p = 1.3333558146e-3f;
    p = fmaf(p, f, 9.6181291077e-3f);
    p = fmaf(p, f, 5.5504108664e-2f);
    p = fmaf(p, f, 2.4022650696e-1f);
    p = fmaf(p, f, 6.9314718056e-1f);
    p = fmaf(p, f, 1.0f);
    return p * __int_as_float((k + 127) << 23);
}

// ---------------------------------------------------------------------------
// Kernel 1 (merged conversions):
//   z = 0..3 : W [K,N] fp32 -> W^T [N,K] bf16 hi/lo  (Wq,Wk,Wv,Wo)
//   z = 4..7 : x slab (z-4)*1024 rows -> xhi/xlo bf16 (same layout)
// ---------------------------------------------------------------------------
__global__ __launch_bounds__(256)
void conv_all(const float* __restrict__ x,
              const float* __restrict__ W0, const float* __restrict__ W1,
              const float* __restrict__ W2, const float* __restrict__ W3,
              __nv_bfloat16* __restrict__ xhi, __nv_bfloat16* __restrict__ xlo,
              __nv_bfloat16* __restrict__ whi, __nv_bfloat16* __restrict__ wlo)
{
    __shared__ float tile[32][33];
    const int z = blockIdx.z;

    if (z >= 4) {
        const int c  = blockIdx.x * 32 + threadIdx.x;
        const int r0 = (z - 4) * 1024 + blockIdx.y * 32 + threadIdx.y;
#pragma unroll
        for (int j = 0; j < 32; j += 8) {
            const size_t idx = (size_t)(r0 + j) * EMBED + c;
            float v = x[idx];
            __nv_bfloat16 h, l;
            split_bf16(v, h, l);
            xhi[idx] = h;
            xlo[idx] = l;
        }
        return;
    }

    const float* W = W0;
    if (z == 1) W = W1;
    else if (z == 2) W = W2;
    else if (z == 3) W = W3;

    const int xc = blockIdx.x * 32 + threadIdx.x;
    const int yc = blockIdx.y * 32 + threadIdx.y;
#pragma unroll
    for (int j = 0; j < 32; j += 8)
        tile[threadIdx.y + j][threadIdx.x] = W[(size_t)(yc + j) * EMBED + xc];
    __syncthreads();

    const int xo = blockIdx.y * 32 + threadIdx.x;
    const int yo = blockIdx.x * 32 + threadIdx.y;
    const size_t zo = (size_t)z * EMBED * EMBED;
#pragma unroll
    for (int j = 0; j < 32; j += 8) {
        float v = tile[threadIdx.x][threadIdx.y + j];
        __nv_bfloat16 h, l;
        split_bf16(v, h, l);
        whi[zo + (size_t)(yo + j) * EMBED + xo] = h;
        wlo[zo + (size_t)(yo + j) * EMBED + xo] = l;
    }
}

// ---------------------------------------------------------------------------
// Kernel 2: bf16x3 GEMM on mma.sync.m16n8k16 + cp.async 2-stage pipeline
//   (unchanged R11/R13 configuration)
// ---------------------------------------------------------------------------
#define TSTR  40                     // padded k-stride (bf16 elems)
#define GT    (128 * TSTR * 2)       // tile bytes (10240)
#define GSTG  (4 * GT)               // stage bytes (40960)

__device__ __forceinline__ void cpa_tile(uint32_t sbase,
                                         const __nv_bfloat16* __restrict__ g,
                                         int tid)
{
#pragma unroll
    for (int it = 0; it < 2; it++) {
        const int c   = tid + it * 256;
        const int r   = c >> 2;
        const int col = (c & 3) << 3;
        cp16(sbase + (uint32_t)(r * TSTR + col) * 2, g + (size_t)r * EMBED + col);
    }
}

template<int SPLIT>
__global__ __launch_bounds__(256, 2)
void gemm_mma(const __nv_bfloat16* __restrict__ Ahi, const __nv_bfloat16* __restrict__ Alo,
              const __nv_bfloat16* __restrict__ Bh0, const __nv_bfloat16* __restrict__ Bh1,
              const __nv_bfloat16* __restrict__ Bh2,
              const __nv_bfloat16* __restrict__ Bl0, const __nv_bfloat16* __restrict__ Bl1,
              const __nv_bfloat16* __restrict__ Bl2,
              const float* __restrict__ c0, const float* __restrict__ c1,
              const float* __restrict__ c2,
              float* __restrict__ F0,
              __nv_bfloat16* __restrict__ H0, __nv_bfloat16* __restrict__ H1,
              __nv_bfloat16* __restrict__ H2,
              __nv_bfloat16* __restrict__ L0, __nv_bfloat16* __restrict__ L1,
              __nv_bfloat16* __restrict__ L2)
{
    extern __shared__ __align__(16) __nv_bfloat16 gsm[];
    const uint32_t sb = smem_u32(gsm);

    const __nv_bfloat16* Bhi = Bh0;
    const __nv_bfloat16* Blo = Bl0;
    const float* bias = c0;
    __nv_bfloat16* Dh = H0;
    __nv_bfloat16* Dl = L0;
    if (blockIdx.z == 1)      { Bhi = Bh1; Blo = Bl1; bias = c1; Dh = H1; Dl = L1; }
    else if (blockIdx.z == 2) { Bhi = Bh2; Blo = Bl2; bias = c2; Dh = H2; Dl = L2; }

    const int tid    = threadIdx.x;
    const int lane   = tid & 31;
    const int wid    = tid >> 5;
    const int warp_m = wid >> 2;
    const int warp_n = wid & 3;
    const int bm     = blockIdx.y * 128;
    const int bn     = blockIdx.x * 128;

    const uint32_t aRow = warp_m * 64 + (lane & 15);
    const uint32_t aOff = aRow * (TSTR * 2) + ((lane >> 4) << 4);
    const uint32_t bg   = lane >> 3;
    const uint32_t bRow = warp_n * 32 + ((bg >> 1) << 3) + (lane & 7);
    const uint32_t bOff = bRow * (TSTR * 2) + ((bg & 1) << 4);

    float acc[4][4][4];
#pragma unroll
    for (int i = 0; i < 4; i++)
#pragma unroll
        for (int j = 0; j < 4; j++)
#pragma unroll
            for (int q = 0; q < 4; q++) acc[i][j][q] = 0.0f;

    const __nv_bfloat16* gAh = Ahi + (size_t)bm * EMBED;
    const __nv_bfloat16* gAl = Alo + (size_t)bm * EMBED;
    const __nv_bfloat16* gBh = Bhi + (size_t)bn * EMBED;
    const __nv_bfloat16* gBl = Blo + (size_t)bn * EMBED;

    // prefetch stage 0
    {
        cpa_tile(sb,          gAh, tid);
        cpa_tile(sb + GT,     gAl, tid);
        cpa_tile(sb + 2 * GT, gBh, tid);
        cpa_tile(sb + 3 * GT, gBl, tid);
    }
    CP_COMMIT();

    for (int kb = 0; kb < EMBED / 32; kb++) {
        if (kb + 1 < EMBED / 32) {
            const int kc = (kb + 1) * 32;
            const uint32_t stB = sb + ((kb + 1) & 1) * GSTG;
            cpa_tile(stB,          gAh + kc, tid);
            cpa_tile(stB + GT,     gAl + kc, tid);
            cpa_tile(stB + 2 * GT, gBh + kc, tid);
            cpa_tile(stB + 3 * GT, gBl + kc, tid);
        }
        CP_COMMIT();
        CP_WAIT1();
        __syncthreads();

        const uint32_t stB = sb + (kb & 1) * GSTG;
        const uint32_t aHb = stB + aOff;
        const uint32_t aLb = stB + GT + aOff;
        const uint32_t bHb = stB + 2 * GT + bOff;
        const uint32_t bLb = stB + 3 * GT + bOff;

#pragma unroll
        for (int ks = 0; ks < 2; ks++) {
            uint32_t ah[4][4], al[4][4], bh[4][2], bl[4][2];
#pragma unroll
            for (int mi = 0; mi < 4; mi++) {
                const uint32_t d = mi * (16 * TSTR * 2) + ks * 32;
                ldsm_x4(aHb + d, ah[mi][0], ah[mi][1], ah[mi][2], ah[mi][3]);
                ldsm_x4(aLb + d, al[mi][0], al[mi][1], al[mi][2], al[mi][3]);
            }
#pragma unroll
            for (int np = 0; np < 2; np++) {
                const uint32_t d = np * (16 * TSTR * 2) + ks * 32;
                ldsm_x4(bHb + d, bh[np*2][0], bh[np*2][1], bh[np*2+1][0], bh[np*2+1][1]);
                ldsm_x4(bLb + d, bl[np*2][0], bl[np*2][1], bl[np*2+1][0], bl[np*2+1][1]);
            }
#pragma unroll
            for (int mi = 0; mi < 4; mi++)
#pragma unroll
                for (int ni = 0; ni < 4; ni++)
                    mma16816(acc[mi][ni], ah[mi], bh[ni]);
#pragma unroll
            for (int mi = 0; mi < 4; mi++)
#pragma unroll
                for (int ni = 0; ni < 4; ni++)
                    mma16816(acc[mi][ni], ah[mi], bl[ni]);
#pragma unroll
            for (int mi = 0; mi < 4; mi++)
#pragma unroll
                for (int ni = 0; ni < 4; ni++)
                    mma16816(acc[mi][ni], al[mi], bh[ni]);
        }
        __syncthreads();
    }

#pragma unroll
    for (int ni = 0; ni < 4; ni++) {
        const int col = bn + warp_n * 32 + ni * 8 + ((lane & 3) << 1);
        const float2 bv = *(const float2*)(bias + col);
#pragma unroll
        for (int mi = 0; mi < 4; mi++) {
            const int row = bm + warp_m * 64 + mi * 16 + (lane >> 2);
            const float a0 = acc[mi][ni][0] + bv.x;
            const float a1 = acc[mi][ni][1] + bv.y;
            const float a2 = acc[mi][ni][2] + bv.x;
            const float a3 = acc[mi][ni][3] + bv.y;
            if (SPLIT) {
                uint32_t h01, l01, h23, l23;
                split2(a0, a1, h01, l01);
                split2(a2, a3, h23, l23);
                *(uint32_t*)(Dh + (size_t)row * EMBED + col)       = h01;
                *(uint32_t*)(Dl + (size_t)row * EMBED + col)       = l01;
                *(uint32_t*)(Dh + (size_t)(row + 8) * EMBED + col) = h23;
                *(uint32_t*)(Dl + (size_t)(row + 8) * EMBED + col) = l23;
            } else {
                float2 o0, o1;
                o0.x = a0; o0.y = a1; o1.x = a2; o1.y = a3;
                *(float2*)(F0 + (size_t)row * EMBED + col)       = o0;
                *(float2*)(F0 + (size_t)(row + 8) * EMBED + col) = o1;
            }
        }
    }
}

// ---------------------------------------------------------------------------
// Kernel 3: tensor-core flash attention (causal), 128x128 tiles.
//   256 threads (8 warps, 16 q-rows each), K/V hi/lo double-buffered cp.async.
//   Per 128 keys: softmax fixed costs, syncs, and per-thread cp.async halved
//   vs the 64-wide version. 1 CTA/SM @ 184 KB smem (flash is occupancy-
//   insensitive per R10/R11 measurements).
//   smem: Qh | Ql | st0{Kh,Kl,Vh,Vl} | st1{Kh,Kl,Vh,Vl}, tiles 128 x FSTR.
// ---------------------------------------------------------------------------
#define FSTR  72                    // padded row stride (bf16)
#define FT128 (128 * FSTR * 2)      // tile bytes (18432)

__device__ __forceinline__ void cpa128(uint32_t sbase,
                                       const __nv_bfloat16* __restrict__ g,
                                       int tid)
{
#pragma unroll
    for (int it = 0; it < 4; it++) {
        const int idx = tid + it * 256;
        const int r = idx >> 3, c = (idx & 7) << 3;
        cp16(sbase + (uint32_t)(r * FSTR + c) * 2, g + (size_t)r * EMBED + c);
    }
}

__global__ __launch_bounds__(256, 1)
void flash_attn(const __nv_bfloat16* __restrict__ Qh, const __nv_bfloat16* __restrict__ Ql,
                const __nv_bfloat16* __restrict__ Kh, const __nv_bfloat16* __restrict__ Kl,
                const __nv_bfloat16* __restrict__ Vh, const __nv_bfloat16* __restrict__ Vl,
                __nv_bfloat16* __restrict__ Oh, __nv_bfloat16* __restrict__ Ol)
{
    extern __shared__ __align__(16) __nv_bfloat16 sm[];
    const uint32_t sb = smem_u32(sm);

    const int tid  = threadIdx.x;
    const int lane = tid & 31;
    const int wid  = tid >> 5;                     // 0..7, warp owns 16 q-rows
    const int qt   = gridDim.x - 1 - blockIdx.x;   // heavy tiles first
    const int h    = blockIdx.y;
    const int b    = blockIdx.z;

    const size_t base = (size_t)b * TSEQ * EMBED + (size_t)h * HDIM;
    const int q0 = qt * 128;

    // ---- prefetch K/V tile j=0 (128 rows) into stage 0 ----
    {
        const uint32_t stB = sb + 2 * FT128;
        cpa128(stB,             Kh + base, tid);
        cpa128(stB + FT128,     Kl + base, tid);
        cpa128(stB + 2 * FT128, Vh + base, tid);
        cpa128(stB + 3 * FT128, Vl + base, tid);
    }
    CP_COMMIT();

    // ---- load Q tile (128 rows, hi/lo) and cache A-frags ----
    {
        const __nv_bfloat16* gq  = Qh + base + (size_t)q0 * EMBED;
        const __nv_bfloat16* gql = Ql + base + (size_t)q0 * EMBED;
        __nv_bfloat16* sQh = sm;
        __nv_bfloat16* sQl = sm + 128 * FSTR;
#pragma unroll
        for (int it = 0; it < 4; it++) {
            const int idx = tid + it * 256;
            const int r = idx >> 3, c = (idx & 7) << 3;
            *(uint4*)(sQh + r * FSTR + c) = *(const uint4*)(gq  + (size_t)r * EMBED + c);
            *(uint4*)(sQl + r * FSTR + c) = *(const uint4*)(gql + (size_t)r * EMBED + c);
        }
    }
    __syncthreads();

    uint32_t qfh[4][4], qfl[4][4];
    {
        const uint32_t aOff = ((wid * 16 + (lane & 15)) * FSTR + ((lane >> 4) << 3)) * 2;
        const uint32_t ah = sb + aOff;
        const uint32_t al = sb + FT128 + aOff;
#pragma unroll
        for (int kf = 0; kf < 4; kf++) {
            ldsm_x4(ah + kf * 32, qfh[kf][0], qfh[kf][1], qfh[kf][2], qfh[kf][3]);
            ldsm_x4(al + kf * 32, qfl[kf][0], qfl[kf][1], qfl[kf][2], qfl[kf][3]);
        }
    }

    // B-frag lane addressing (K normal, V trans)
    const uint32_t bg = lane >> 3;
    const uint32_t kOff = ((((bg >> 1) << 3) + (lane & 7)) * FSTR + ((bg & 1) << 3)) * 2;
    const uint32_t vOff = ((((bg & 1) << 3) + (lane & 7)) * FSTR + ((bg >> 1) << 3)) * 2;

    float ofr[8][4];
#pragma unroll
    for (int nf = 0; nf < 8; nf++)
#pragma unroll
        for (int q = 0; q < 4; q++) ofr[nf][q] = 0.0f;
    float m0 = -1e30f, m1 = -1e30f, l0 = 0.0f, l1 = 0.0f;

    const float SC = 0.18033688011112042f;   // 0.125 * log2(e)
    const int r0loc = wid * 16 + (lane >> 2);

    for (int j = 0; j <= qt; j++) {
        // prefetch next K/V tile into the other stage
        if (j < qt) {
            const size_t koff = base + (size_t)((j + 1) * 128) * EMBED;
            const uint32_t stB = sb + 2 * FT128 + ((j + 1) & 1) * 4 * FT128;
            cpa128(stB,             Kh + koff, tid);
            cpa128(stB + FT128,     Kl + koff, tid);
            cpa128(stB + 2 * FT128, Vh + koff, tid);
            cpa128(stB + 3 * FT128, Vl + koff, tid);
        }
        CP_COMMIT();
        CP_WAIT1();
        __syncthreads();

        const uint32_t stB = sb + 2 * FT128 + (j & 1) * 4 * FT128;

        // ---- S = Q K^T (bf16x3), 16 q-rows x 128 k-cols per warp ----
        float sfr[16][4];
#pragma unroll
        for (int nf = 0; nf < 16; nf++)
#pragma unroll
            for (int q = 0; q < 4; q++) sfr[nf][q] = 0.0f;

#pragma unroll
        for (int half = 0; half < 2; half++) {     // K rows 0-63, 64-127
            const uint32_t kh0 = stB + half * (64 * FSTR * 2) + kOff;
            const uint32_t kl0 = stB + FT128 + half * (64 * FSTR * 2) + kOff;
            float (*sf)[4] = &sfr[half * 8];
#pragma unroll
            for (int ks = 0; ks < 4; ks++) {
                uint32_t bh[16], bl[16];
#pragma unroll
                for (int nb = 0; nb < 4; nb++) {
                    const uint32_t d = nb * (16 * FSTR * 2) + ks * 32;
                    ldsm_x4(kh0 + d, bh[nb*4+0], bh[nb*4+1], bh[nb*4+2], bh[nb*4+3]);
                    ldsm_x4(kl0 + d, bl[nb*4+0], bl[nb*4+1], bl[nb*4+2], bl[nb*4+3]);
                }
#pragma unroll
                for (int nf = 0; nf < 8; nf++)
                    mma16816(sf[nf], qfh[ks], &bh[nf*2]);
#pragma unroll
                for (int nf = 0; nf < 8; nf++)
                    mma16816(sf[nf], qfh[ks], &bl[nf*2]);
#pragma unroll
                for (int nf = 0; nf < 8; nf++)
                    mma16816(sf[nf], qfl[ks], &bh[nf*2]);
            }
        }

        // ---- scale + causal mask (within-tile indices 0..127) ----
        if (j == qt) {
#pragma unroll
            for (int nf = 0; nf < 16; nf++)
#pragma unroll
                for (int q = 0; q < 4; q++) {
                    const int col = nf * 8 + ((lane & 3) << 1) + (q & 1);
                    const int row = r0loc + ((q >> 1) << 3);
                    sfr[nf][q] = (col <= row) ? sfr[nf][q] * SC : -1e30f;
                }
        } else {
#pragma unroll
            for (int nf = 0; nf < 16; nf++)
#pragma unroll
                for (int q = 0; q < 4; q++) sfr[nf][q] *= SC;
        }

        // ---- online softmax (base-2, FFMA-pipe exp) ----
        float mx0 = -1e30f, mx1 = -1e30f;
#pragma unroll
        for (int nf = 0; nf < 16; nf++) {
            mx0 = fmaxf(mx0, fmaxf(sfr[nf][0], sfr[nf][1]));
            mx1 = fmaxf(mx1, fmaxf(sfr[nf][2], sfr[nf][3]));
        }
        mx0 = fmaxf(mx0, __shfl_xor_sync(0xffffffffu, mx0, 1));
        mx0 = fmaxf(mx0, __shfl_xor_sync(0xffffffffu, mx0, 2));
        mx1 = fmaxf(mx1, __shfl_xor_sync(0xffffffffu, mx1, 1));
        mx1 = fmaxf(mx1, __shfl_xor_sync(0xffffffffu, mx1, 2));

        const float mn0 = fmaxf(m0, mx0);
        const float mn1 = fmaxf(m1, mx1);
        const float a0 = fexp2(m0 - mn0);
        const float a1 = fexp2(m1 - mn1);
        m0 = mn0; m1 = mn1;

        float rs0 = 0.0f, rs1 = 0.0f;
#pragma unroll
        for (int nf = 0; nf < 16; nf++) {
            sfr[nf][0] = fexp2(sfr[nf][0] - mn0);
            sfr[nf][1] = fexp2(sfr[nf][1] - mn0);
            sfr[nf][2] = fexp2(sfr[nf][2] - mn1);
            sfr[nf][3] = fexp2(sfr[nf][3] - mn1);
            rs0 += sfr[nf][0] + sfr[nf][1];
            rs1 += sfr[nf][2] + sfr[nf][3];
        }
        rs0 += __shfl_xor_sync(0xffffffffu, rs0, 1);
        rs0 += __shfl_xor_sync(0xffffffffu, rs0, 2);
        rs1 += __shfl_xor_sync(0xffffffffu, rs1, 1);
        rs1 += __shfl_xor_sync(0xffffffffu, rs1, 2);
        l0 = l0 * a0 + rs0;
        l1 = l1 * a1 + rs1;

#pragma unroll
        for (int nf = 0; nf < 8; nf++) {
            ofr[nf][0] *= a0; ofr[nf][1] *= a0;
            ofr[nf][2] *= a1; ofr[nf][3] *= a1;
        }

        // ---- O += P V (bf16x3): pack P per kf, V via ldmatrix.trans ----
        const uint32_t vh0 = stB + 2 * FT128 + vOff;
        const uint32_t vl0 = stB + 3 * FT128 + vOff;
#pragma unroll
        for (int kf = 0; kf < 8; kf++) {           // 8 x 16 keys
            uint32_t pah[4], pal[4];
            split2(sfr[2*kf][0],   sfr[2*kf][1],   pah[0], pal[0]);
            split2(sfr[2*kf][2],   sfr[2*kf][3],   pah[1], pal[1]);
            split2(sfr[2*kf+1][0], sfr[2*kf+1][1], pah[2], pal[2]);
            split2(sfr[2*kf+1][2], sfr[2*kf+1][3], pah[3], pal[3]);

            uint32_t vh[16], vl[16];
#pragma unroll
            for (int nb = 0; nb < 4; nb++) {
                const uint32_t d = kf * (16 * FSTR * 2) + nb * 32;
                ldsm_x4_t(vh0 + d, vh[nb*4+0], vh[nb*4+1], vh[nb*4+2], vh[nb*4+3]);
                ldsm_x4_t(vl0 + d, vl[nb*4+0], vl[nb*4+1], vl[nb*4+2], vl[nb*4+3]);
            }
#pragma unroll
            for (int nf = 0; nf < 8; nf++)
                mma16816(ofr[nf], pah, &vh[nf*2]);
#pragma unroll
            for (int nf = 0; nf < 8; nf++)
                mma16816(ofr[nf], pal, &vh[nf*2]);
#pragma unroll
            for (int nf = 0; nf < 8; nf++)
                mma16816(ofr[nf], pah, &vl[nf*2]);
        }
        __syncthreads();
    }

    // ---- finalize: O /= l, write bf16 hi/lo split ----
    const float i0 = 1.0f / l0;
    const float i1 = 1.0f / l1;
    const int row0 = q0 + r0loc;
#pragma unroll
    for (int nf = 0; nf < 8; nf++) {
        const int col = nf * 8 + ((lane & 3) << 1);
        uint32_t h01, l01, h23, l23;
        split2(ofr[nf][0] * i0, ofr[nf][1] * i0, h01, l01);
        split2(ofr[nf][2] * i1, ofr[nf][3] * i1, h23, l23);
        const size_t o0 = base + (size_t)row0 * EMBED + col;
        const size_t o1 = base + (size_t)(row0 + 8) * EMBED + col;
        *(uint32_t*)(Oh + o0) = h01;
        *(uint32_t*)(Ol + o0) = l01;
        *(uint32_t*)(Oh + o1) = h23;
        *(uint32_t*)(Ol + o1) = l23;
    }
}

// ---------------------------------------------------------------------------
// Launch
// ---------------------------------------------------------------------------
extern "C" void kernel_launch(void* const* d_in, const int* in_sizes, int n_in,
                              void* d_out, int out_size)
{
    (void)in_sizes; (void)n_in; (void)out_size;
    const float* x  = (const float*)d_in[0];
    const float* Wq = (const float*)d_in[1];
    const float* bq = (const float*)d_in[2];
    const float* Wk = (const float*)d_in[3];
    const float* bk = (const float*)d_in[4];
    const float* Wv = (const float*)d_in[5];
    const float* bv = (const float*)d_in[6];
    const float* Wo = (const float*)d_in[7];
    const float* bo = (const float*)d_in[8];
    float* out = (float*)d_out;

    void *p;
    cudaGetSymbolAddress(&p, g_xhi); __nv_bfloat16* xhi = (__nv_bfloat16*)p;
    cudaGetSymbolAddress(&p, g_xlo); __nv_bfloat16* xlo = (__nv_bfloat16*)p;
    cudaGetSymbolAddress(&p, g_Qh);  __nv_bfloat16* Qh  = (__nv_bfloat16*)p;
    cudaGetSymbolAddress(&p, g_Ql);  __nv_bfloat16* Ql  = (__nv_bfloat16*)p;
    cudaGetSymbolAddress(&p, g_Kh);  __nv_bfloat16* Kh  = (__nv_bfloat16*)p;
    cudaGetSymbolAddress(&p, g_Kl);  __nv_bfloat16* Kl  = (__nv_bfloat16*)p;
    cudaGetSymbolAddress(&p, g_Vh);  __nv_bfloat16* Vh  = (__nv_bfloat16*)p;
    cudaGetSymbolAddress(&p, g_Vl);  __nv_bfloat16* Vl  = (__nv_bfloat16*)p;
    cudaGetSymbolAddress(&p, g_ahi); __nv_bfloat16* ahi = (__nv_bfloat16*)p;
    cudaGetSymbolAddress(&p, g_alo); __nv_bfloat16* alo = (__nv_bfloat16*)p;
    cudaGetSymbolAddress(&p, g_whi); __nv_bfloat16* whi = (__nv_bfloat16*)p;
    cudaGetSymbolAddress(&p, g_wlo); __nv_bfloat16* wlo = (__nv_bfloat16*)p;

    const size_t WSZ = (size_t)EMBED * EMBED;
    const int GEMM_SMEM  = 2 * GSTG;        // 81920 B
    const int FLASH_SMEM = 10 * FT128;      // 184320 B -> 1 CTA/SM
    cudaFuncSetAttribute(gemm_mma<1>, cudaFuncAttributeMaxDynamicSharedMemorySize,
                         GEMM_SMEM);
    cudaFuncSetAttribute(gemm_mma<0>, cudaFuncAttributeMaxDynamicSharedMemorySize,
                         GEMM_SMEM);
    cudaFuncSetAttribute(flash_attn, cudaFuncAttributeMaxDynamicSharedMemorySize,
                         FLASH_SMEM);

    // 1) fp32 -> bf16 hi/lo conversions (single merged launch)
    conv_all<<<dim3(32, 32, 8), dim3(32, 8)>>>(x, Wq, Wk, Wv, Wo,
                                               xhi, xlo, whi, wlo);

    // 2) fused QKV projection -> bf16 hi/lo split outputs
    dim3 g1(EMBED / 128, NTOK / 128, 3);
    gemm_mma<1><<<g1, 256, GEMM_SMEM>>>(xhi, xlo,
                                        whi, whi + WSZ, whi + 2 * WSZ,
                                        wlo, wlo + WSZ, wlo + 2 * WSZ,
                                        bq, bk, bv, nullptr,
                                        Qh, Kh, Vh, Ql, Kl, Vl);

    // 3) tensor-core causal flash attention (128x128 tiles)
    dim3 g2(TSEQ / 128, NH, 2);
    flash_attn<<<g2, 256, FLASH_SMEM>>>(Qh, Ql, Kh, Kl, Vh, Vl, ahi, alo);

    // 4) output projection -> fp32
    dim3 g3(EMBED / 128, NTOK / 128, 1);
    gemm_mma<0><<<g3, 256, GEMM_SMEM>>>(ahi, alo,
                                        whi + 3 * WSZ, whi + 3 * WSZ, whi + 3 * WSZ,
                                        wlo + 3 * WSZ, wlo + 3 * WSZ, wlo + 3 * WSZ,
                                        bo, bo, bo, out,
                                        nullptr, nullptr, nullptr, nullptr,
                                        nullptr, nullptr);
}

// round 15
// speedup vs baseline: 1.0367x; 1.0367x over previous
#include <cuda_runtime.h>
#include <cuda_bf16.h>
#include <math.h>
#include <stdint.h>

// Problem constants
#define NTOK  4096      // B*T
#define TSEQ  2048
#define EMBED 1024
#define NH    16
#define HDIM  64

// ---------------------------------------------------------------------------
// Scratch (device globals: allocation-free per harness rules)
// ---------------------------------------------------------------------------
__device__ __nv_bfloat16 g_xhi[(size_t)NTOK * EMBED];
__device__ __nv_bfloat16 g_xlo[(size_t)NTOK * EMBED];
__device__ __nv_bfloat16 g_Qh[(size_t)NTOK * EMBED];
__device__ __nv_bfloat16 g_Ql[(size_t)NTOK * EMBED];
__device__ __nv_bfloat16 g_Kh[(size_t)NTOK * EMBED];
__device__ __nv_bfloat16 g_Kl[(size_t)NTOK * EMBED];
__device__ __nv_bfloat16 g_Vh[(size_t)NTOK * EMBED];
__device__ __nv_bfloat16 g_Vl[(size_t)NTOK * EMBED];
__device__ __nv_bfloat16 g_ahi[(size_t)NTOK * EMBED];
__device__ __nv_bfloat16 g_alo[(size_t)NTOK * EMBED];
__device__ __nv_bfloat16 g_whi[(size_t)4 * EMBED * EMBED];  // Wq^T,Wk^T,Wv^T,Wo^T
__device__ __nv_bfloat16 g_wlo[(size_t)4 * EMBED * EMBED];

// ---------------------------------------------------------------------------
// PTX helpers (compute_103-safe: ldmatrix + mma.sync + cp.async)
// ---------------------------------------------------------------------------
__device__ __forceinline__ uint32_t smem_u32(const void* p) {
    uint32_t a;
    asm("{ .reg .u64 t; cvta.to.shared.u64 t, %1; cvt.u32.u64 %0, t; }"
        : "=r"(a) : "l"(p));
    return a;
}

__device__ __forceinline__ void cp16(uint32_t dst, const void* src) {
    asm volatile("cp.async.cg.shared.global [%0], [%1], 16;"
                 :: "r"(dst), "l"(src));
}
#define CP_COMMIT() asm volatile("cp.async.commit_group;" ::: "memory")
#define CP_WAIT0()  asm volatile("cp.async.wait_group 0;" ::: "memory")
#define CP_WAIT1()  asm volatile("cp.async.wait_group 1;" ::: "memory")

__device__ __forceinline__ void ldsm_x4(uint32_t addr, uint32_t& r0, uint32_t& r1,
                                        uint32_t& r2, uint32_t& r3) {
    asm volatile("ldmatrix.sync.aligned.m8n8.x4.shared.b16 {%0,%1,%2,%3}, [%4];"
                 : "=r"(r0), "=r"(r1), "=r"(r2), "=r"(r3) : "r"(addr));
}

__device__ __forceinline__ void ldsm_x4_t(uint32_t addr, uint32_t& r0, uint32_t& r1,
                                          uint32_t& r2, uint32_t& r3) {
    asm volatile("ldmatrix.sync.aligned.m8n8.x4.trans.shared.b16 {%0,%1,%2,%3}, [%4];"
                 : "=r"(r0), "=r"(r1), "=r"(r2), "=r"(r3) : "r"(addr));
}

__device__ __forceinline__ void mma16816(float* d, const uint32_t* a,
                                         const uint32_t* b) {
    asm volatile(
        "mma.sync.aligned.m16n8k16.row.col.f32.bf16.bf16.f32 "
        "{%0,%1,%2,%3}, {%4,%5,%6,%7}, {%8,%9}, {%0,%1,%2,%3};"
        : "+f"(d[0]), "+f"(d[1]), "+f"(d[2]), "+f"(d[3])
        : "r"(a[0]), "r"(a[1]), "r"(a[2]), "r"(a[3]), "r"(b[0]), "r"(b[1]));
}

// fp32 -> (bf16 hi, bf16 lo) split
__device__ __forceinline__ void split_bf16(float v, __nv_bfloat16& h, __nv_bfloat16& l) {
    h = __float2bfloat16(v);
    l = __float2bfloat16(v - __bfloat162float(h));
}

__device__ __forceinline__ void split2(float a, float b, uint32_t& hi, uint32_t& lo) {
    __nv_bfloat16 ha = __float2bfloat16(a);
    __nv_bfloat16 hb = __float2bfloat16(b);
    __nv_bfloat162 hp = __halves2bfloat162(ha, hb);
    hi = *reinterpret_cast<uint32_t*>(&hp);
    __nv_bfloat162 lp = __floats2bfloat162_rn(a - __bfloat162float(ha),
                                              b - __bfloat162float(hb));
    lo = *reinterpret_cast<uint32_t*>(&lp);
}

// Software exp2 on the FMA pipe (no MUFU). rel err ~2e-6.
__device__ __forceinline__ float fexp2(float x) {
    x = fmaxf(x, -125.0f);
    float t = __fadd_rn(x, 12582912.0f);
    int   k = __float_as_int(t) - 0x4B400000;
    float f = __fsub_rn(x, __fsub_rn(t, 12582912.0f));
    float p = 1.3333558146e-3f;
    p = fmaf(p, f, 9.6181291077e-3f);
    p = fmaf(p, f, 5.5504108664e-2f);
    p = fmaf(p, f, 2.4022650696e-1f);
    p = fmaf(p, f, 6.9314718056e-1f);
    p = fmaf(p, f, 1.0f);
    return p * __int_as_float((k + 127) << 23);
}

// ---------------------------------------------------------------------------
// Kernel 1 (merged conversions):
//   z = 0..3 : W [K,N] fp32 -> W^T [N,K] bf16 hi/lo  (Wq,Wk,Wv,Wo)
//   z = 4..7 : x slab (z-4)*1024 rows -> xhi/xlo bf16 (same layout)
// ---------------------------------------------------------------------------
__global__ __launch_bounds__(256)
void conv_all(const float* __restrict__ x,
              const float* __restrict__ W0, const float* __restrict__ W1,
              const float* __restrict__ W2, const float* __restrict__ W3,
              __nv_bfloat16* __restrict__ xhi, __nv_bfloat16* __restrict__ xlo,
              __nv_bfloat16* __restrict__ whi, __nv_bfloat16* __restrict__ wlo)
{
    __shared__ float tile[32][33];
    const int z = blockIdx.z;

    if (z >= 4) {
        const int c  = blockIdx.x * 32 + threadIdx.x;
        const int r0 = (z - 4) * 1024 + blockIdx.y * 32 + threadIdx.y;
#pragma unroll
        for (int j = 0; j < 32; j += 8) {
            const size_t idx = (size_t)(r0 + j) * EMBED + c;
            float v = x[idx];
            __nv_bfloat16 h, l;
            split_bf16(v, h, l);
            xhi[idx] = h;
            xlo[idx] = l;
        }
        return;
    }

    const float* W = W0;
    if (z == 1) W = W1;
    else if (z == 2) W = W2;
    else if (z == 3) W = W3;

    const int xc = blockIdx.x * 32 + threadIdx.x;
    const int yc = blockIdx.y * 32 + threadIdx.y;
#pragma unroll
    for (int j = 0; j < 32; j += 8)
        tile[threadIdx.y + j][threadIdx.x] = W[(size_t)(yc + j) * EMBED + xc];
    __syncthreads();

    const int xo = blockIdx.y * 32 + threadIdx.x;
    const int yo = blockIdx.x * 32 + threadIdx.y;
    const size_t zo = (size_t)z * EMBED * EMBED;
#pragma unroll
    for (int j = 0; j < 32; j += 8) {
        float v = tile[threadIdx.x][threadIdx.y + j];
        __nv_bfloat16 h, l;
        split_bf16(v, h, l);
        whi[zo + (size_t)(yo + j) * EMBED + xo] = h;
        wlo[zo + (size_t)(yo + j) * EMBED + xo] = l;
    }
}

// ---------------------------------------------------------------------------
// Kernel 2: bf16x3 GEMM on mma.sync.m16n8k16 + cp.async 2-stage pipeline.
//   R15: ONE barrier per kb-step. Order per iter: wait0 -> sync -> issue
//   prefetch(kb+1) -> compute(kb). The prefetch targets the stage whose
//   readers (iter kb-1) have all passed this iteration's barrier, so the
//   trailing sync is unnecessary.
// ---------------------------------------------------------------------------
#define TSTR  40                     // padded k-stride (bf16 elems)
#define GT    (128 * TSTR * 2)       // tile bytes (10240)
#define GSTG  (4 * GT)               // stage bytes (40960)

__device__ __forceinline__ void cpa_tile(uint32_t sbase,
                                         const __nv_bfloat16* __restrict__ g,
                                         int tid)
{
#pragma unroll
    for (int it = 0; it < 2; it++) {
        const int c   = tid + it * 256;
        const int r   = c >> 2;
        const int col = (c & 3) << 3;
        cp16(sbase + (uint32_t)(r * TSTR + col) * 2, g + (size_t)r * EMBED + col);
    }
}

template<int SPLIT>
__global__ __launch_bounds__(256, 2)
void gemm_mma(const __nv_bfloat16* __restrict__ Ahi, const __nv_bfloat16* __restrict__ Alo,
              const __nv_bfloat16* __restrict__ Bh0, const __nv_bfloat16* __restrict__ Bh1,
              const __nv_bfloat16* __restrict__ Bh2,
              const __nv_bfloat16* __restrict__ Bl0, const __nv_bfloat16* __restrict__ Bl1,
              const __nv_bfloat16* __restrict__ Bl2,
              const float* __restrict__ c0, const float* __restrict__ c1,
              const float* __restrict__ c2,
              float* __restrict__ F0,
              __nv_bfloat16* __restrict__ H0, __nv_bfloat16* __restrict__ H1,
              __nv_bfloat16* __restrict__ H2,
              __nv_bfloat16* __restrict__ L0, __nv_bfloat16* __restrict__ L1,
              __nv_bfloat16* __restrict__ L2)
{
    extern __shared__ __align__(16) __nv_bfloat16 gsm[];
    const uint32_t sb = smem_u32(gsm);

    const __nv_bfloat16* Bhi = Bh0;
    const __nv_bfloat16* Blo = Bl0;
    const float* bias = c0;
    __nv_bfloat16* Dh = H0;
    __nv_bfloat16* Dl = L0;
    if (blockIdx.z == 1)      { Bhi = Bh1; Blo = Bl1; bias = c1; Dh = H1; Dl = L1; }
    else if (blockIdx.z == 2) { Bhi = Bh2; Blo = Bl2; bias = c2; Dh = H2; Dl = L2; }

    const int tid    = threadIdx.x;
    const int lane   = tid & 31;
    const int wid    = tid >> 5;
    const int warp_m = wid >> 2;
    const int warp_n = wid & 3;
    const int bm     = blockIdx.y * 128;
    const int bn     = blockIdx.x * 128;

    const uint32_t aRow = warp_m * 64 + (lane & 15);
    const uint32_t aOff = aRow * (TSTR * 2) + ((lane >> 4) << 4);
    const uint32_t bg   = lane >> 3;
    const uint32_t bRow = warp_n * 32 + ((bg >> 1) << 3) + (lane & 7);
    const uint32_t bOff = bRow * (TSTR * 2) + ((bg & 1) << 4);

    float acc[4][4][4];
#pragma unroll
    for (int i = 0; i < 4; i++)
#pragma unroll
        for (int j = 0; j < 4; j++)
#pragma unroll
            for (int q = 0; q < 4; q++) acc[i][j][q] = 0.0f;

    const __nv_bfloat16* gAh = Ahi + (size_t)bm * EMBED;
    const __nv_bfloat16* gAl = Alo + (size_t)bm * EMBED;
    const __nv_bfloat16* gBh = Bhi + (size_t)bn * EMBED;
    const __nv_bfloat16* gBl = Blo + (size_t)bn * EMBED;

    // prologue: prefetch stage 0
    {
        cpa_tile(sb,          gAh, tid);
        cpa_tile(sb + GT,     gAl, tid);
        cpa_tile(sb + 2 * GT, gBh, tid);
        cpa_tile(sb + 3 * GT, gBl, tid);
    }
    CP_COMMIT();

    for (int kb = 0; kb < EMBED / 32; kb++) {
        // stage kb ready; all readers of the OTHER stage have passed this barrier
        CP_WAIT0();
        __syncthreads();

        // prefetch kb+1 into the other stage (overlaps compute below)
        if (kb + 1 < EMBED / 32) {
            const int kc = (kb + 1) * 32;
            const uint32_t stB = sb + ((kb + 1) & 1) * GSTG;
            cpa_tile(stB,          gAh + kc, tid);
            cpa_tile(stB + GT,     gAl + kc, tid);
            cpa_tile(stB + 2 * GT, gBh + kc, tid);
            cpa_tile(stB + 3 * GT, gBl + kc, tid);
            CP_COMMIT();
        }

        const uint32_t stB = sb + (kb & 1) * GSTG;
        const uint32_t aHb = stB + aOff;
        const uint32_t aLb = stB + GT + aOff;
        const uint32_t bHb = stB + 2 * GT + bOff;
        const uint32_t bLb = stB + 3 * GT + bOff;

#pragma unroll
        for (int ks = 0; ks < 2; ks++) {
            uint32_t ah[4][4], al[4][4], bh[4][2], bl[4][2];
#pragma unroll
            for (int mi = 0; mi < 4; mi++) {
                const uint32_t d = mi * (16 * TSTR * 2) + ks * 32;
                ldsm_x4(aHb + d, ah[mi][0], ah[mi][1], ah[mi][2], ah[mi][3]);
                ldsm_x4(aLb + d, al[mi][0], al[mi][1], al[mi][2], al[mi][3]);
            }
#pragma unroll
            for (int np = 0; np < 2; np++) {
                const uint32_t d = np * (16 * TSTR * 2) + ks * 32;
                ldsm_x4(bHb + d, bh[np*2][0], bh[np*2][1], bh[np*2+1][0], bh[np*2+1][1]);
                ldsm_x4(bLb + d, bl[np*2][0], bl[np*2][1], bl[np*2+1][0], bl[np*2+1][1]);
            }
            // term-outer ordering: consecutive MMAs hit independent accumulators
#pragma unroll
            for (int mi = 0; mi < 4; mi++)
#pragma unroll
                for (int ni = 0; ni < 4; ni++)
                    mma16816(acc[mi][ni], ah[mi], bh[ni]);
#pragma unroll
            for (int mi = 0; mi < 4; mi++)
#pragma unroll
                for (int ni = 0; ni < 4; ni++)
                    mma16816(acc[mi][ni], ah[mi], bl[ni]);
#pragma unroll
            for (int mi = 0; mi < 4; mi++)
#pragma unroll
                for (int ni = 0; ni < 4; ni++)
                    mma16816(acc[mi][ni], al[mi], bh[ni]);
        }
        // no trailing __syncthreads: next iteration's barrier provides it
    }

#pragma unroll
    for (int ni = 0; ni < 4; ni++) {
        const int col = bn + warp_n * 32 + ni * 8 + ((lane & 3) << 1);
        const float2 bv = *(const float2*)(bias + col);
#pragma unroll
        for (int mi = 0; mi < 4; mi++) {
            const int row = bm + warp_m * 64 + mi * 16 + (lane >> 2);
            const float a0 = acc[mi][ni][0] + bv.x;
            const float a1 = acc[mi][ni][1] + bv.y;
            const float a2 = acc[mi][ni][2] + bv.x;
            const float a3 = acc[mi][ni][3] + bv.y;
            if (SPLIT) {
                uint32_t h01, l01, h23, l23;
                split2(a0, a1, h01, l01);
                split2(a2, a3, h23, l23);
                *(uint32_t*)(Dh + (size_t)row * EMBED + col)       = h01;
                *(uint32_t*)(Dl + (size_t)row * EMBED + col)       = l01;
                *(uint32_t*)(Dh + (size_t)(row + 8) * EMBED + col) = h23;
                *(uint32_t*)(Dl + (size_t)(row + 8) * EMBED + col) = l23;
            } else {
                float2 o0, o1;
                o0.x = a0; o0.y = a1; o1.x = a2; o1.y = a3;
                *(float2*)(F0 + (size_t)row * EMBED + col)       = o0;
                *(float2*)(F0 + (size_t)(row + 8) * EMBED + col) = o1;
            }
        }
    }
}

// ---------------------------------------------------------------------------
// Kernel 3: tensor-core flash attention (causal) — FROZEN R13/R10 config
//   (64x64 tiles, K/V hi/lo double-buffered, 2 CTAs/SM; best measured 203.5us)
// ---------------------------------------------------------------------------
#define FSTR 72                  // padded row stride (bf16)
#define FT   (64 * FSTR * 2)     // tile bytes (9216)

__device__ __forceinline__ void cpa64(uint32_t sbase,
                                      const __nv_bfloat16* __restrict__ g,
                                      int tid)
{
#pragma unroll
    for (int it = 0; it < 4; it++) {
        const int idx = tid + it * 128;
        const int r = idx >> 3, c = (idx & 7) << 3;
        cp16(sbase + (uint32_t)(r * FSTR + c) * 2, g + (size_t)r * EMBED + c);
    }
}

__global__ __launch_bounds__(128, 2)
void flash_attn(const __nv_bfloat16* __restrict__ Qh, const __nv_bfloat16* __restrict__ Ql,
                const __nv_bfloat16* __restrict__ Kh, const __nv_bfloat16* __restrict__ Kl,
                const __nv_bfloat16* __restrict__ Vh, const __nv_bfloat16* __restrict__ Vl,
                __nv_bfloat16* __restrict__ Oh, __nv_bfloat16* __restrict__ Ol)
{
    extern __shared__ __align__(16) __nv_bfloat16 sm[];
    const uint32_t sb = smem_u32(sm);

    const int tid  = threadIdx.x;
    const int lane = tid & 31;
    const int wid  = tid >> 5;
    const int qt   = gridDim.x - 1 - blockIdx.x;   // heavy tiles first
    const int h    = blockIdx.y;
    const int b    = blockIdx.z;

    const size_t base = (size_t)b * TSEQ * EMBED + (size_t)h * HDIM;
    const int q0 = qt * 64;

    // ---- prefetch K/V tile j=0 into stage 0 ----
    {
        const uint32_t stB = sb + 2 * FT;
        cpa64(stB,          Kh + base, tid);
        cpa64(stB + FT,     Kl + base, tid);
        cpa64(stB + 2 * FT, Vh + base, tid);
        cpa64(stB + 3 * FT, Vl + base, tid);
    }
    CP_COMMIT();

    // ---- load Q tile (hi/lo) and cache A-frags in registers ----
    {
        const __nv_bfloat16* gq  = Qh + base + (size_t)q0 * EMBED;
        const __nv_bfloat16* gql = Ql + base + (size_t)q0 * EMBED;
        __nv_bfloat16* sQh = sm;
        __nv_bfloat16* sQl = sm + 64 * FSTR;
#pragma unroll
        for (int it = 0; it < 4; it++) {
            const int idx = tid + it * 128;
            const int r = idx >> 3, c = (idx & 7) << 3;
            *(uint4*)(sQh + r * FSTR + c) = *(const uint4*)(gq  + (size_t)r * EMBED + c);
            *(uint4*)(sQl + r * FSTR + c) = *(const uint4*)(gql + (size_t)r * EMBED + c);
        }
    }
    __syncthreads();

    uint32_t qfh[4][4], qfl[4][4];
    {
        const uint32_t aOff = ((wid * 16 + (lane & 15)) * FSTR + ((lane >> 4) << 3)) * 2;
        const uint32_t ah = sb + aOff;
        const uint32_t al = sb + FT + aOff;
#pragma unroll
        for (int kf = 0; kf < 4; kf++) {
            ldsm_x4(ah + kf * 32, qfh[kf][0], qfh[kf][1], qfh[kf][2], qfh[kf][3]);
            ldsm_x4(al + kf * 32, qfl[kf][0], qfl[kf][1], qfl[kf][2], qfl[kf][3]);
        }
    }

    // B-frag lane addressing (K normal, V trans)
    const uint32_t bg = lane >> 3;
    const uint32_t kOff = ((((bg >> 1) << 3) + (lane & 7)) * FSTR + ((bg & 1) << 3)) * 2;
    const uint32_t vOff = ((((bg & 1) << 3) + (lane & 7)) * FSTR + ((bg >> 1) << 3)) * 2;

    float ofr[8][4];
#pragma unroll
    for (int nf = 0; nf < 8; nf++)
#pragma unroll
        for (int q = 0; q < 4; q++) ofr[nf][q] = 0.0f;
    float m0 = -1e30f, m1 = -1e30f, l0 = 0.0f, l1 = 0.0f;

    const float SC = 0.18033688011112042f;   // 0.125 * log2(e)
    const int r0loc = wid * 16 + (lane >> 2);

    for (int j = 0; j <= qt; j++) {
        // prefetch next K/V tile into the other stage
        if (j < qt) {
            const size_t koff = base + (size_t)((j + 1) * 64) * EMBED;
            const uint32_t stB = sb + 2 * FT + ((j + 1) & 1) * 4 * FT;
            cpa64(stB,          Kh + koff, tid);
            cpa64(stB + FT,     Kl + koff, tid);
            cpa64(stB + 2 * FT, Vh + koff, tid);
            cpa64(stB + 3 * FT, Vl + koff, tid);
        }
        CP_COMMIT();
        CP_WAIT1();
        __syncthreads();

        const uint32_t stB = sb + 2 * FT + (j & 1) * 4 * FT;

        // ---- S = Q K^T (bf16x3) ----
        float sfr[8][4];
#pragma unroll
        for (int nf = 0; nf < 8; nf++)
#pragma unroll
            for (int q = 0; q < 4; q++) sfr[nf][q] = 0.0f;

        const uint32_t kh0 = stB + kOff;
        const uint32_t kl0 = stB + FT + kOff;
#pragma unroll
        for (int ks = 0; ks < 4; ks++) {
            uint32_t bh[16], bl[16];
#pragma unroll
            for (int nb = 0; nb < 4; nb++) {
                const uint32_t d = nb * (16 * FSTR * 2) + ks * 32;
                ldsm_x4(kh0 + d, bh[nb*4+0], bh[nb*4+1], bh[nb*4+2], bh[nb*4+3]);
                ldsm_x4(kl0 + d, bl[nb*4+0], bl[nb*4+1], bl[nb*4+2], bl[nb*4+3]);
            }
#pragma unroll
            for (int nf = 0; nf < 8; nf++)
                mma16816(sfr[nf], qfh[ks], &bh[nf*2]);
#pragma unroll
            for (int nf = 0; nf < 8; nf++)
                mma16816(sfr[nf], qfh[ks], &bl[nf*2]);
#pragma unroll
            for (int nf = 0; nf < 8; nf++)
                mma16816(sfr[nf], qfl[ks], &bh[nf*2]);
        }

        // ---- scale + causal mask ----
        if (j == qt) {
#pragma unroll
            for (int nf = 0; nf < 8; nf++)
#pragma unroll
                for (int q = 0; q < 4; q++) {
                    const int col = nf * 8 + ((lane & 3) << 1) + (q & 1);
                    const int row = r0loc + ((q >> 1) << 3);
                    sfr[nf][q] = (col <= row) ? sfr[nf][q] * SC : -1e30f;
                }
        } else {
#pragma unroll
            for (int nf = 0; nf < 8; nf++)
#pragma unroll
                for (int q = 0; q < 4; q++) sfr[nf][q] *= SC;
        }

        // ---- online softmax (base-2, FFMA-pipe exp) ----
        float mx0 = -1e30f, mx1 = -1e30f;
#pragma unroll
        for (int nf = 0; nf < 8; nf++) {
            mx0 = fmaxf(mx0, fmaxf(sfr[nf][0], sfr[nf][1]));
            mx1 = fmaxf(mx1, fmaxf(sfr[nf][2], sfr[nf][3]));
        }
        mx0 = fmaxf(mx0, __shfl_xor_sync(0xffffffffu, mx0, 1));
        mx0 = fmaxf(mx0, __shfl_xor_sync(0xffffffffu, mx0, 2));
        mx1 = fmaxf(mx1, __shfl_xor_sync(0xffffffffu, mx1, 1));
        mx1 = fmaxf(mx1, __shfl_xor_sync(0xffffffffu, mx1, 2));

        const float mn0 = fmaxf(m0, mx0);
        const float mn1 = fmaxf(m1, mx1);
        const float a0 = fexp2(m0 - mn0);
        const float a1 = fexp2(m1 - mn1);
        m0 = mn0; m1 = mn1;

        float rs0 = 0.0f, rs1 = 0.0f;
#pragma unroll
        for (int nf = 0; nf < 8; nf++) {
            sfr[nf][0] = fexp2(sfr[nf][0] - mn0);
            sfr[nf][1] = fexp2(sfr[nf][1] - mn0);
            sfr[nf][2] = fexp2(sfr[nf][2] - mn1);
            sfr[nf][3] = fexp2(sfr[nf][3] - mn1);
            rs0 += sfr[nf][0] + sfr[nf][1];
            rs1 += sfr[nf][2] + sfr[nf][3];
        }
        rs0 += __shfl_xor_sync(0xffffffffu, rs0, 1);
        rs0 += __shfl_xor_sync(0xffffffffu, rs0, 2);
        rs1 += __shfl_xor_sync(0xffffffffu, rs1, 1);
        rs1 += __shfl_xor_sync(0xffffffffu, rs1, 2);
        l0 = l0 * a0 + rs0;
        l1 = l1 * a1 + rs1;

#pragma unroll
        for (int nf = 0; nf < 8; nf++) {
            ofr[nf][0] *= a0; ofr[nf][1] *= a0;
            ofr[nf][2] *= a1; ofr[nf][3] *= a1;
        }

        // ---- pack P into A-frags ----
        uint32_t pah[4][4], pal[4][4];
#pragma unroll
        for (int kf = 0; kf < 4; kf++) {
            split2(sfr[2*kf][0],   sfr[2*kf][1],   pah[kf][0], pal[kf][0]);
            split2(sfr[2*kf][2],   sfr[2*kf][3],   pah[kf][1], pal[kf][1]);
            split2(sfr[2*kf+1][0], sfr[2*kf+1][1], pah[kf][2], pal[kf][2]);
            split2(sfr[2*kf+1][2], sfr[2*kf+1][3], pah[kf][3], pal[kf][3]);
        }

        // ---- O += P V (bf16x3, V via ldmatrix.trans) ----
        const uint32_t vh0 = stB + 2 * FT + vOff;
        const uint32_t vl0 = stB + 3 * FT + vOff;
#pragma unroll
        for (int kf = 0; kf < 4; kf++) {
            uint32_t vh[16], vl[16];
#pragma unroll
            for (int nb = 0; nb < 4; nb++) {
                const uint32_t d = kf * (16 * FSTR * 2) + nb * 32;
                ldsm_x4_t(vh0 + d, vh[nb*4+0], vh[nb*4+1], vh[nb*4+2], vh[nb*4+3]);
                ldsm_x4_t(vl0 + d, vl[nb*4+0], vl[nb*4+1], vl[nb*4+2], vl[nb*4+3]);
            }
#pragma unroll
            for (int nf = 0; nf < 8; nf++)
                mma16816(ofr[nf], pah[kf], &vh[nf*2]);
#pragma unroll
            for (int nf = 0; nf < 8; nf++)
                mma16816(ofr[nf], pal[kf], &vh[nf*2]);
#pragma unroll
            for (int nf = 0; nf < 8; nf++)
                mma16816(ofr[nf], pah[kf], &vl[nf*2]);
        }
        __syncthreads();
    }

    // ---- finalize: O /= l, write bf16 hi/lo split ----
    const float i0 = 1.0f / l0;
    const float i1 = 1.0f / l1;
    const int row0 = q0 + r0loc;
#pragma unroll
    for (int nf = 0; nf < 8; nf++) {
        const int col = nf * 8 + ((lane & 3) << 1);
        uint32_t h01, l01, h23, l23;
        split2(ofr[nf][0] * i0, ofr[nf][1] * i0, h01, l01);
        split2(ofr[nf][2] * i1, ofr[nf][3] * i1, h23, l23);
        const size_t o0 = base + (size_t)row0 * EMBED + col;
        const size_t o1 = base + (size_t)(row0 + 8) * EMBED + col;
        *(uint32_t*)(Oh + o0) = h01;
        *(uint32_t*)(Ol + o0) = l01;
        *(uint32_t*)(Oh + o1) = h23;
        *(uint32_t*)(Ol + o1) = l23;
    }
}

// ---------------------------------------------------------------------------
// Launch
// ---------------------------------------------------------------------------
extern "C" void kernel_launch(void* const* d_in, const int* in_sizes, int n_in,
                              void* d_out, int out_size)
{
    (void)in_sizes; (void)n_in; (void)out_size;
    const float* x  = (const float*)d_in[0];
    const float* Wq = (const float*)d_in[1];
    const float* bq = (const float*)d_in[2];
    const float* Wk = (const float*)d_in[3];
    const float* bk = (const float*)d_in[4];
    const float* Wv = (const float*)d_in[5];
    const float* bv = (const float*)d_in[6];
    const float* Wo = (const float*)d_in[7];
    const float* bo = (const float*)d_in[8];
    float* out = (float*)d_out;

    void *p;
    cudaGetSymbolAddress(&p, g_xhi); __nv_bfloat16* xhi = (__nv_bfloat16*)p;
    cudaGetSymbolAddress(&p, g_xlo); __nv_bfloat16* xlo = (__nv_bfloat16*)p;
    cudaGetSymbolAddress(&p, g_Qh);  __nv_bfloat16* Qh  = (__nv_bfloat16*)p;
    cudaGetSymbolAddress(&p, g_Ql);  __nv_bfloat16* Ql  = (__nv_bfloat16*)p;
    cudaGetSymbolAddress(&p, g_Kh);  __nv_bfloat16* Kh  = (__nv_bfloat16*)p;
    cudaGetSymbolAddress(&p, g_Kl);  __nv_bfloat16* Kl  = (__nv_bfloat16*)p;
    cudaGetSymbolAddress(&p, g_Vh);  __nv_bfloat16* Vh  = (__nv_bfloat16*)p;
    cudaGetSymbolAddress(&p, g_Vl);  __nv_bfloat16* Vl  = (__nv_bfloat16*)p;
    cudaGetSymbolAddress(&p, g_ahi); __nv_bfloat16* ahi = (__nv_bfloat16*)p;
    cudaGetSymbolAddress(&p, g_alo); __nv_bfloat16* alo = (__nv_bfloat16*)p;
    cudaGetSymbolAddress(&p, g_whi); __nv_bfloat16* whi = (__nv_bfloat16*)p;
    cudaGetSymbolAddress(&p, g_wlo); __nv_bfloat16* wlo = (__nv_bfloat16*)p;

    const size_t WSZ = (size_t)EMBED * EMBED;
    const int GEMM_SMEM  = 2 * GSTG;       // 81920 B
    const int FLASH_SMEM = 10 * FT;        // 92160 B -> 2 CTAs/SM (best measured)
    cudaFuncSetAttribute(gemm_mma<1>, cudaFuncAttributeMaxDynamicSharedMemorySize,
                         GEMM_SMEM);
    cudaFuncSetAttribute(gemm_mma<0>, cudaFuncAttributeMaxDynamicSharedMemorySize,
                         GEMM_SMEM);
    cudaFuncSetAttribute(flash_attn, cudaFuncAttributeMaxDynamicSharedMemorySize,
                         FLASH_SMEM);

    // 1) fp32 -> bf16 hi/lo conversions (single merged launch)
    conv_all<<<dim3(32, 32, 8), dim3(32, 8)>>>(x, Wq, Wk, Wv, Wo,
                                               xhi, xlo, whi, wlo);

    // 2) fused QKV projection -> bf16 hi/lo split outputs
    dim3 g1(EMBED / 128, NTOK / 128, 3);
    gemm_mma<1><<<g1, 256, GEMM_SMEM>>>(xhi, xlo,
                                        whi, whi + WSZ, whi + 2 * WSZ,
                                        wlo, wlo + WSZ, wlo + 2 * WSZ,
                                        bq, bk, bv, nullptr,
                                        Qh, Kh, Vh, Ql, Kl, Vl);

    // 3) tensor-core causal flash attention (frozen best config)
    dim3 g2(TSEQ / 64, NH, 2);
    flash_attn<<<g2, 128, FLASH_SMEM>>>(Qh, Ql, Kh, Kl, Vh, Vl, ahi, alo);

    // 4) output projection -> fp32
    dim3 g3(EMBED / 128, NTOK / 128, 1);
    gemm_mma<0><<<g3, 256, GEMM_SMEM>>>(ahi, alo,
                                        whi + 3 * WSZ, whi + 3 * WSZ, whi + 3 * WSZ,
                                        wlo + 3 * WSZ, wlo + 3 * WSZ, wlo + 3 * WSZ,
                                        bo, bo, bo, out,
                                        nullptr, nullptr, nullptr, nullptr,
                                        nullptr, nullptr);
}

// round 16
// speedup vs baseline: 1.2436x; 1.1996x over previous
#include <cuda_runtime.h>
#include <cuda_bf16.h>
#include <cuda_fp16.h>
#include <math.h>
#include <stdint.h>

// Problem constants
#define NTOK  4096      // B*T
#define TSEQ  2048
#define EMBED 1024
#define NH    16
#define HDIM  64

// ---------------------------------------------------------------------------
// Scratch (device globals: allocation-free per harness rules)
// ---------------------------------------------------------------------------
__device__ __half g_xh[(size_t)NTOK * EMBED];
__device__ __half g_xl[(size_t)NTOK * EMBED];
__device__ __nv_bfloat16 g_Qh[(size_t)NTOK * EMBED];
__device__ __nv_bfloat16 g_Ql[(size_t)NTOK * EMBED];
__device__ __nv_bfloat16 g_Kh[(size_t)NTOK * EMBED];
__device__ __nv_bfloat16 g_Kl[(size_t)NTOK * EMBED];
__device__ __nv_bfloat16 g_Vh[(size_t)NTOK * EMBED];
__device__ __nv_bfloat16 g_Vl[(size_t)NTOK * EMBED];
__device__ __half g_ah[(size_t)NTOK * EMBED];
__device__ __half g_al[(size_t)NTOK * EMBED];
__device__ __half g_wh[(size_t)4 * EMBED * EMBED];  // Wq^T,Wk^T,Wv^T,Wo^T fp16
// (B-side lo dropped: fp16 rounding residual ~2^-12, within error budget)

// ---------------------------------------------------------------------------
// PTX helpers (compute_103-safe: ldmatrix + mma.sync + cp.async)
// ---------------------------------------------------------------------------
__device__ __forceinline__ uint32_t smem_u32(const void* p) {
    uint32_t a;
    asm("{ .reg .u64 t; cvta.to.shared.u64 t, %1; cvt.u32.u64 %0, t; }"
        : "=r"(a) : "l"(p));
    return a;
}

__device__ __forceinline__ void cp16(uint32_t dst, const void* src) {
    asm volatile("cp.async.cg.shared.global [%0], [%1], 16;"
                 :: "r"(dst), "l"(src));
}
#define CP_COMMIT() asm volatile("cp.async.commit_group;" ::: "memory")
#define CP_WAIT0()  asm volatile("cp.async.wait_group 0;" ::: "memory")
#define CP_WAIT1()  asm volatile("cp.async.wait_group 1;" ::: "memory")

__device__ __forceinline__ void ldsm_x4(uint32_t addr, uint32_t& r0, uint32_t& r1,
                                        uint32_t& r2, uint32_t& r3) {
    asm volatile("ldmatrix.sync.aligned.m8n8.x4.shared.b16 {%0,%1,%2,%3}, [%4];"
                 : "=r"(r0), "=r"(r1), "=r"(r2), "=r"(r3) : "r"(addr));
}

__device__ __forceinline__ void ldsm_x4_t(uint32_t addr, uint32_t& r0, uint32_t& r1,
                                          uint32_t& r2, uint32_t& r3) {
    asm volatile("ldmatrix.sync.aligned.m8n8.x4.trans.shared.b16 {%0,%1,%2,%3}, [%4];"
                 : "=r"(r0), "=r"(r1), "=r"(r2), "=r"(r3) : "r"(addr));
}

// bf16 MMA (flash attention)
__device__ __forceinline__ void mma16816(float* d, const uint32_t* a,
                                         const uint32_t* b) {
    asm volatile(
        "mma.sync.aligned.m16n8k16.row.col.f32.bf16.bf16.f32 "
        "{%0,%1,%2,%3}, {%4,%5,%6,%7}, {%8,%9}, {%0,%1,%2,%3};"
        : "+f"(d[0]), "+f"(d[1]), "+f"(d[2]), "+f"(d[3])
        : "r"(a[0]), "r"(a[1]), "r"(a[2]), "r"(a[3]), "r"(b[0]), "r"(b[1]));
}

// fp16 MMA (projection GEMMs)
__device__ __forceinline__ void mma16816h(float* d, const uint32_t* a,
                                          const uint32_t* b) {
    asm volatile(
        "mma.sync.aligned.m16n8k16.row.col.f32.f16.f16.f32 "
        "{%0,%1,%2,%3}, {%4,%5,%6,%7}, {%8,%9}, {%0,%1,%2,%3};"
        : "+f"(d[0]), "+f"(d[1]), "+f"(d[2]), "+f"(d[3])
        : "r"(a[0]), "r"(a[1]), "r"(a[2]), "r"(a[3]), "r"(b[0]), "r"(b[1]));
}

// fp32 -> (bf16 hi, bf16 lo) split / packed pair (flash path)
__device__ __forceinline__ void split2(float a, float b, uint32_t& hi, uint32_t& lo) {
    __nv_bfloat16 ha = __float2bfloat16(a);
    __nv_bfloat16 hb = __float2bfloat16(b);
    __nv_bfloat162 hp = __halves2bfloat162(ha, hb);
    hi = *reinterpret_cast<uint32_t*>(&hp);
    __nv_bfloat162 lp = __floats2bfloat162_rn(a - __bfloat162float(ha),
                                              b - __bfloat162float(hb));
    lo = *reinterpret_cast<uint32_t*>(&lp);
}

// fp32 -> (fp16 hi, fp16 lo) packed pair (GEMM A-side path)
__device__ __forceinline__ void split2h(float a, float b, uint32_t& hi, uint32_t& lo) {
    __half ha = __float2half_rn(a);
    __half hb = __float2half_rn(b);
    __half2 hp = __halves2half2(ha, hb);
    hi = *reinterpret_cast<uint32_t*>(&hp);
    __half2 lp = __floats2half2_rn(a - __half2float(ha),
                                   b - __half2float(hb));
    lo = *reinterpret_cast<uint32_t*>(&lp);
}

// Software exp2 on the FMA pipe (no MUFU). rel err ~2e-6.
__device__ __forceinline__ float fexp2(float x) {
    x = fmaxf(x, -125.0f);
    float t = __fadd_rn(x, 12582912.0f);
    int   k = __float_as_int(t) - 0x4B400000;
    float f = __fsub_rn(x, __fsub_rn(t, 12582912.0f));
    float p = 1.3333558146e-3f;
    p = fmaf(p, f, 9.6181291077e-3f);
    p = fmaf(p, f, 5.5504108664e-2f);
    p = fmaf(p, f, 2.4022650696e-1f);
    p = fmaf(p, f, 6.9314718056e-1f);
    p = fmaf(p, f, 1.0f);
    return p * __int_as_float((k + 127) << 23);
}

// ---------------------------------------------------------------------------
// Kernel 1 (merged conversions):
//   z = 0..3 : W [K,N] fp32 -> W^T [N,K] fp16 (hi only)
//   z = 4..7 : x slab (z-4)*1024 rows -> xh/xl fp16 2-level split
// ---------------------------------------------------------------------------
__global__ __launch_bounds__(256)
void conv_all(const float* __restrict__ x,
              const float* __restrict__ W0, const float* __restrict__ W1,
              const float* __restrict__ W2, const float* __restrict__ W3,
              __half* __restrict__ xh, __half* __restrict__ xl,
              __half* __restrict__ wh)
{
    __shared__ float tile[32][33];
    const int z = blockIdx.z;

    if (z >= 4) {
        const int c  = blockIdx.x * 32 + threadIdx.x;
        const int r0 = (z - 4) * 1024 + blockIdx.y * 32 + threadIdx.y;
#pragma unroll
        for (int j = 0; j < 32; j += 8) {
            const size_t idx = (size_t)(r0 + j) * EMBED + c;
            float v = x[idx];
            __half h = __float2half_rn(v);
            xh[idx] = h;
            xl[idx] = __float2half_rn(v - __half2float(h));
        }
        return;
    }

    const float* W = W0;
    if (z == 1) W = W1;
    else if (z == 2) W = W2;
    else if (z == 3) W = W3;

    const int xc = blockIdx.x * 32 + threadIdx.x;
    const int yc = blockIdx.y * 32 + threadIdx.y;
#pragma unroll
    for (int j = 0; j < 32; j += 8)
        tile[threadIdx.y + j][threadIdx.x] = W[(size_t)(yc + j) * EMBED + xc];
    __syncthreads();

    const int xo = blockIdx.y * 32 + threadIdx.x;
    const int yo = blockIdx.x * 32 + threadIdx.y;
    const size_t zo = (size_t)z * EMBED * EMBED;
#pragma unroll
    for (int j = 0; j < 32; j += 8)
        wh[zo + (size_t)(yo + j) * EMBED + xo] =
            __float2half_rn(tile[threadIdx.x][threadIdx.y + j]);
}

// ---------------------------------------------------------------------------
// Kernel 2: fp16 2-term GEMM on mma.sync.m16n8k16 + cp.async 2-stage pipeline.
//   D = Ah*Bh + Al*Bh  (A = activations split 2-level fp16, B = weights fp16)
//   Per kb: 20 LDSM, 64 MMA (was 24/96 with bf16x3). Stage = 3 tiles (30 KB).
// ---------------------------------------------------------------------------
#define TSTR  40                     // padded k-stride (elems)
#define GT    (128 * TSTR * 2)       // tile bytes (10240)
#define GSTG  (3 * GT)               // stage bytes (30720)

__device__ __forceinline__ void cpa_tile(uint32_t sbase,
                                         const __half* __restrict__ g,
                                         int tid)
{
#pragma unroll
    for (int it = 0; it < 2; it++) {
        const int c   = tid + it * 256;
        const int r   = c >> 2;
        const int col = (c & 3) << 3;
        cp16(sbase + (uint32_t)(r * TSTR + col) * 2, g + (size_t)r * EMBED + col);
    }
}

template<int SPLIT>
__global__ __launch_bounds__(256, 2)
void gemm_mma(const __half* __restrict__ Ahi, const __half* __restrict__ Alo,
              const __half* __restrict__ Bh0, const __half* __restrict__ Bh1,
              const __half* __restrict__ Bh2,
              const float* __restrict__ c0, const float* __restrict__ c1,
              const float* __restrict__ c2,
              float* __restrict__ F0,
              __nv_bfloat16* __restrict__ H0, __nv_bfloat16* __restrict__ H1,
              __nv_bfloat16* __restrict__ H2,
              __nv_bfloat16* __restrict__ L0, __nv_bfloat16* __restrict__ L1,
              __nv_bfloat16* __restrict__ L2)
{
    extern __shared__ __align__(16) __half gsm[];
    const uint32_t sb = smem_u32(gsm);

    const __half* Bhi = Bh0;
    const float* bias = c0;
    __nv_bfloat16* Dh = H0;
    __nv_bfloat16* Dl = L0;
    if (blockIdx.z == 1)      { Bhi = Bh1; bias = c1; Dh = H1; Dl = L1; }
    else if (blockIdx.z == 2) { Bhi = Bh2; bias = c2; Dh = H2; Dl = L2; }

    const int tid    = threadIdx.x;
    const int lane   = tid & 31;
    const int wid    = tid >> 5;
    const int warp_m = wid >> 2;
    const int warp_n = wid & 3;
    const int bm     = blockIdx.y * 128;
    const int bn     = blockIdx.x * 128;

    const uint32_t aRow = warp_m * 64 + (lane & 15);
    const uint32_t aOff = aRow * (TSTR * 2) + ((lane >> 4) << 4);
    const uint32_t bg   = lane >> 3;
    const uint32_t bRow = warp_n * 32 + ((bg >> 1) << 3) + (lane & 7);
    const uint32_t bOff = bRow * (TSTR * 2) + ((bg & 1) << 4);

    float acc[4][4][4];
#pragma unroll
    for (int i = 0; i < 4; i++)
#pragma unroll
        for (int j = 0; j < 4; j++)
#pragma unroll
            for (int q = 0; q < 4; q++) acc[i][j][q] = 0.0f;

    const __half* gAh = Ahi + (size_t)bm * EMBED;
    const __half* gAl = Alo + (size_t)bm * EMBED;
    const __half* gBh = Bhi + (size_t)bn * EMBED;

    // prologue: prefetch stage 0
    {
        cpa_tile(sb,          gAh, tid);
        cpa_tile(sb + GT,     gAl, tid);
        cpa_tile(sb + 2 * GT, gBh, tid);
    }
    CP_COMMIT();

    for (int kb = 0; kb < EMBED / 32; kb++) {
        CP_WAIT0();
        __syncthreads();

        // prefetch kb+1 into the other stage (overlaps compute below)
        if (kb + 1 < EMBED / 32) {
            const int kc = (kb + 1) * 32;
            const uint32_t stB = sb + ((kb + 1) & 1) * GSTG;
            cpa_tile(stB,          gAh + kc, tid);
            cpa_tile(stB + GT,     gAl + kc, tid);
            cpa_tile(stB + 2 * GT, gBh + kc, tid);
            CP_COMMIT();
        }

        const uint32_t stB = sb + (kb & 1) * GSTG;
        const uint32_t aHb = stB + aOff;
        const uint32_t aLb = stB + GT + aOff;
        const uint32_t bHb = stB + 2 * GT + bOff;

#pragma unroll
        for (int ks = 0; ks < 2; ks++) {
            uint32_t ah[4][4], al[4][4], bh[4][2];
#pragma unroll
            for (int mi = 0; mi < 4; mi++) {
                const uint32_t d = mi * (16 * TSTR * 2) + ks * 32;
                ldsm_x4(aHb + d, ah[mi][0], ah[mi][1], ah[mi][2], ah[mi][3]);
                ldsm_x4(aLb + d, al[mi][0], al[mi][1], al[mi][2], al[mi][3]);
            }
#pragma unroll
            for (int np = 0; np < 2; np++) {
                const uint32_t d = np * (16 * TSTR * 2) + ks * 32;
                ldsm_x4(bHb + d, bh[np*2][0], bh[np*2][1], bh[np*2+1][0], bh[np*2+1][1]);
            }
            // term-outer ordering: consecutive MMAs hit independent accumulators
#pragma unroll
            for (int mi = 0; mi < 4; mi++)
#pragma unroll
                for (int ni = 0; ni < 4; ni++)
                    mma16816h(acc[mi][ni], ah[mi], bh[ni]);
#pragma unroll
            for (int mi = 0; mi < 4; mi++)
#pragma unroll
                for (int ni = 0; ni < 4; ni++)
                    mma16816h(acc[mi][ni], al[mi], bh[ni]);
        }
    }

#pragma unroll
    for (int ni = 0; ni < 4; ni++) {
        const int col = bn + warp_n * 32 + ni * 8 + ((lane & 3) << 1);
        const float2 bv = *(const float2*)(bias + col);
#pragma unroll
        for (int mi = 0; mi < 4; mi++) {
            const int row = bm + warp_m * 64 + mi * 16 + (lane >> 2);
            const float a0 = acc[mi][ni][0] + bv.x;
            const float a1 = acc[mi][ni][1] + bv.y;
            const float a2 = acc[mi][ni][2] + bv.x;
            const float a3 = acc[mi][ni][3] + bv.y;
            if (SPLIT) {
                uint32_t h01, l01, h23, l23;
                split2(a0, a1, h01, l01);
                split2(a2, a3, h23, l23);
                *(uint32_t*)(Dh + (size_t)row * EMBED + col)       = h01;
                *(uint32_t*)(Dl + (size_t)row * EMBED + col)       = l01;
                *(uint32_t*)(Dh + (size_t)(row + 8) * EMBED + col) = h23;
                *(uint32_t*)(Dl + (size_t)(row + 8) * EMBED + col) = l23;
            } else {
                float2 o0, o1;
                o0.x = a0; o0.y = a1; o1.x = a2; o1.y = a3;
                *(float2*)(F0 + (size_t)row * EMBED + col)       = o0;
                *(float2*)(F0 + (size_t)(row + 8) * EMBED + col) = o1;
            }
        }
    }
}

// ---------------------------------------------------------------------------
// Kernel 3: tensor-core flash attention (causal) — FROZEN bf16x3 internals
//   (64x64 tiles, K/V hi/lo double-buffered, 2 CTAs/SM; best measured 203.5us)
//   Only change: output written as fp16 hi/lo split (feeds fp16 O-projection).
// ---------------------------------------------------------------------------
#define FSTR 72                  // padded row stride (bf16)
#define FT   (64 * FSTR * 2)     // tile bytes (9216)

__device__ __forceinline__ void cpa64(uint32_t sbase,
                                      const __nv_bfloat16* __restrict__ g,
                                      int tid)
{
#pragma unroll
    for (int it = 0; it < 4; it++) {
        const int idx = tid + it * 128;
        const int r = idx >> 3, c = (idx & 7) << 3;
        cp16(sbase + (uint32_t)(r * FSTR + c) * 2, g + (size_t)r * EMBED + c);
    }
}

__global__ __launch_bounds__(128, 2)
void flash_attn(const __nv_bfloat16* __restrict__ Qh, const __nv_bfloat16* __restrict__ Ql,
                const __nv_bfloat16* __restrict__ Kh, const __nv_bfloat16* __restrict__ Kl,
                const __nv_bfloat16* __restrict__ Vh, const __nv_bfloat16* __restrict__ Vl,
                __half* __restrict__ Oh, __half* __restrict__ Ol)
{
    extern __shared__ __align__(16) __nv_bfloat16 sm[];
    const uint32_t sb = smem_u32(sm);

    const int tid  = threadIdx.x;
    const int lane = tid & 31;
    const int wid  = tid >> 5;
    const int qt   = gridDim.x - 1 - blockIdx.x;   // heavy tiles first
    const int h    = blockIdx.y;
    const int b    = blockIdx.z;

    const size_t base = (size_t)b * TSEQ * EMBED + (size_t)h * HDIM;
    const int q0 = qt * 64;

    // ---- prefetch K/V tile j=0 into stage 0 ----
    {
        const uint32_t stB = sb + 2 * FT;
        cpa64(stB,          Kh + base, tid);
        cpa64(stB + FT,     Kl + base, tid);
        cpa64(stB + 2 * FT, Vh + base, tid);
        cpa64(stB + 3 * FT, Vl + base, tid);
    }
    CP_COMMIT();

    // ---- load Q tile (hi/lo) and cache A-frags in registers ----
    {
        const __nv_bfloat16* gq  = Qh + base + (size_t)q0 * EMBED;
        const __nv_bfloat16* gql = Ql + base + (size_t)q0 * EMBED;
        __nv_bfloat16* sQh = sm;
        __nv_bfloat16* sQl = sm + 64 * FSTR;
#pragma unroll
        for (int it = 0; it < 4; it++) {
            const int idx = tid + it * 128;
            const int r = idx >> 3, c = (idx & 7) << 3;
            *(uint4*)(sQh + r * FSTR + c) = *(const uint4*)(gq  + (size_t)r * EMBED + c);
            *(uint4*)(sQl + r * FSTR + c) = *(const uint4*)(gql + (size_t)r * EMBED + c);
        }
    }
    __syncthreads();

    uint32_t qfh[4][4], qfl[4][4];
    {
        const uint32_t aOff = ((wid * 16 + (lane & 15)) * FSTR + ((lane >> 4) << 3)) * 2;
        const uint32_t ah = sb + aOff;
        const uint32_t al = sb + FT + aOff;
#pragma unroll
        for (int kf = 0; kf < 4; kf++) {
            ldsm_x4(ah + kf * 32, qfh[kf][0], qfh[kf][1], qfh[kf][2], qfh[kf][3]);
            ldsm_x4(al + kf * 32, qfl[kf][0], qfl[kf][1], qfl[kf][2], qfl[kf][3]);
        }
    }

    // B-frag lane addressing (K normal, V trans)
    const uint32_t bg = lane >> 3;
    const uint32_t kOff = ((((bg >> 1) << 3) + (lane & 7)) * FSTR + ((bg & 1) << 3)) * 2;
    const uint32_t vOff = ((((bg & 1) << 3) + (lane & 7)) * FSTR + ((bg >> 1) << 3)) * 2;

    float ofr[8][4];
#pragma unroll
    for (int nf = 0; nf < 8; nf++)
#pragma unroll
        for (int q = 0; q < 4; q++) ofr[nf][q] = 0.0f;
    float m0 = -1e30f, m1 = -1e30f, l0 = 0.0f, l1 = 0.0f;

    const float SC = 0.18033688011112042f;   // 0.125 * log2(e)
    const int r0loc = wid * 16 + (lane >> 2);

    for (int j = 0; j <= qt; j++) {
        if (j < qt) {
            const size_t koff = base + (size_t)((j + 1) * 64) * EMBED;
            const uint32_t stB = sb + 2 * FT + ((j + 1) & 1) * 4 * FT;
            cpa64(stB,          Kh + koff, tid);
            cpa64(stB + FT,     Kl + koff, tid);
            cpa64(stB + 2 * FT, Vh + koff, tid);
            cpa64(stB + 3 * FT, Vl + koff, tid);
        }
        CP_COMMIT();
        CP_WAIT1();
        __syncthreads();

        const uint32_t stB = sb + 2 * FT + (j & 1) * 4 * FT;

        // ---- S = Q K^T (bf16x3) ----
        float sfr[8][4];
#pragma unroll
        for (int nf = 0; nf < 8; nf++)
#pragma unroll
            for (int q = 0; q < 4; q++) sfr[nf][q] = 0.0f;

        const uint32_t kh0 = stB + kOff;
        const uint32_t kl0 = stB + FT + kOff;
#pragma unroll
        for (int ks = 0; ks < 4; ks++) {
            uint32_t bh[16], bl[16];
#pragma unroll
            for (int nb = 0; nb < 4; nb++) {
                const uint32_t d = nb * (16 * FSTR * 2) + ks * 32;
                ldsm_x4(kh0 + d, bh[nb*4+0], bh[nb*4+1], bh[nb*4+2], bh[nb*4+3]);
                ldsm_x4(kl0 + d, bl[nb*4+0], bl[nb*4+1], bl[nb*4+2], bl[nb*4+3]);
            }
#pragma unroll
            for (int nf = 0; nf < 8; nf++)
                mma16816(sfr[nf], qfh[ks], &bh[nf*2]);
#pragma unroll
            for (int nf = 0; nf < 8; nf++)
                mma16816(sfr[nf], qfh[ks], &bl[nf*2]);
#pragma unroll
            for (int nf = 0; nf < 8; nf++)
                mma16816(sfr[nf], qfl[ks], &bh[nf*2]);
        }

        // ---- scale + causal mask ----
        if (j == qt) {
#pragma unroll
            for (int nf = 0; nf < 8; nf++)
#pragma unroll
                for (int q = 0; q < 4; q++) {
                    const int col = nf * 8 + ((lane & 3) << 1) + (q & 1);
                    const int row = r0loc + ((q >> 1) << 3);
                    sfr[nf][q] = (col <= row) ? sfr[nf][q] * SC : -1e30f;
                }
        } else {
#pragma unroll
            for (int nf = 0; nf < 8; nf++)
#pragma unroll
                for (int q = 0; q < 4; q++) sfr[nf][q] *= SC;
        }

        // ---- online softmax (base-2, FFMA-pipe exp) ----
        float mx0 = -1e30f, mx1 = -1e30f;
#pragma unroll
        for (int nf = 0; nf < 8; nf++) {
            mx0 = fmaxf(mx0, fmaxf(sfr[nf][0], sfr[nf][1]));
            mx1 = fmaxf(mx1, fmaxf(sfr[nf][2], sfr[nf][3]));
        }
        mx0 = fmaxf(mx0, __shfl_xor_sync(0xffffffffu, mx0, 1));
        mx0 = fmaxf(mx0, __shfl_xor_sync(0xffffffffu, mx0, 2));
        mx1 = fmaxf(mx1, __shfl_xor_sync(0xffffffffu, mx1, 1));
        mx1 = fmaxf(mx1, __shfl_xor_sync(0xffffffffu, mx1, 2));

        const float mn0 = fmaxf(m0, mx0);
        const float mn1 = fmaxf(m1, mx1);
        const float a0 = fexp2(m0 - mn0);
        const float a1 = fexp2(m1 - mn1);
        m0 = mn0; m1 = mn1;

        float rs0 = 0.0f, rs1 = 0.0f;
#pragma unroll
        for (int nf = 0; nf < 8; nf++) {
            sfr[nf][0] = fexp2(sfr[nf][0] - mn0);
            sfr[nf][1] = fexp2(sfr[nf][1] - mn0);
            sfr[nf][2] = fexp2(sfr[nf][2] - mn1);
            sfr[nf][3] = fexp2(sfr[nf][3] - mn1);
            rs0 += sfr[nf][0] + sfr[nf][1];
            rs1 += sfr[nf][2] + sfr[nf][3];
        }
        rs0 += __shfl_xor_sync(0xffffffffu, rs0, 1);
        rs0 += __shfl_xor_sync(0xffffffffu, rs0, 2);
        rs1 += __shfl_xor_sync(0xffffffffu, rs1, 1);
        rs1 += __shfl_xor_sync(0xffffffffu, rs1, 2);
        l0 = l0 * a0 + rs0;
        l1 = l1 * a1 + rs1;

#pragma unroll
        for (int nf = 0; nf < 8; nf++) {
            ofr[nf][0] *= a0; ofr[nf][1] *= a0;
            ofr[nf][2] *= a1; ofr[nf][3] *= a1;
        }

        // ---- pack P into A-frags (bf16 hi/lo) ----
        uint32_t pah[4][4], pal[4][4];
#pragma unroll
        for (int kf = 0; kf < 4; kf++) {
            split2(sfr[2*kf][0],   sfr[2*kf][1],   pah[kf][0], pal[kf][0]);
            split2(sfr[2*kf][2],   sfr[2*kf][3],   pah[kf][1], pal[kf][1]);
            split2(sfr[2*kf+1][0], sfr[2*kf+1][1], pah[kf][2], pal[kf][2]);
            split2(sfr[2*kf+1][2], sfr[2*kf+1][3], pah[kf][3], pal[kf][3]);
        }

        // ---- O += P V (bf16x3, V via ldmatrix.trans) ----
        const uint32_t vh0 = stB + 2 * FT + vOff;
        const uint32_t vl0 = stB + 3 * FT + vOff;
#pragma unroll
        for (int kf = 0; kf < 4; kf++) {
            uint32_t vh[16], vl[16];
#pragma unroll
            for (int nb = 0; nb < 4; nb++) {
                const uint32_t d = kf * (16 * FSTR * 2) + nb * 32;
                ldsm_x4_t(vh0 + d, vh[nb*4+0], vh[nb*4+1], vh[nb*4+2], vh[nb*4+3]);
                ldsm_x4_t(vl0 + d, vl[nb*4+0], vl[nb*4+1], vl[nb*4+2], vl[nb*4+3]);
            }
#pragma unroll
            for (int nf = 0; nf < 8; nf++)
                mma16816(ofr[nf], pah[kf], &vh[nf*2]);
#pragma unroll
            for (int nf = 0; nf < 8; nf++)
                mma16816(ofr[nf], pal[kf], &vh[nf*2]);
#pragma unroll
            for (int nf = 0; nf < 8; nf++)
                mma16816(ofr[nf], pah[kf], &vl[nf*2]);
        }
        __syncthreads();
    }

    // ---- finalize: O /= l, write fp16 hi/lo split (feeds fp16 O-proj) ----
    const float i0 = 1.0f / l0;
    const float i1 = 1.0f / l1;
    const int row0 = q0 + r0loc;
#pragma unroll
    for (int nf = 0; nf < 8; nf++) {
        const int col = nf * 8 + ((lane & 3) << 1);
        uint32_t h01, l01, h23, l23;
        split2h(ofr[nf][0] * i0, ofr[nf][1] * i0, h01, l01);
        split2h(ofr[nf][2] * i1, ofr[nf][3] * i1, h23, l23);
        const size_t o0 = base + (size_t)row0 * EMBED + col;
        const size_t o1 = base + (size_t)(row0 + 8) * EMBED + col;
        *(uint32_t*)(Oh + o0) = h01;
        *(uint32_t*)(Ol + o0) = l01;
        *(uint32_t*)(Oh + o1) = h23;
        *(uint32_t*)(Ol + o1) = l23;
    }
}

// ---------------------------------------------------------------------------
// Launch
// ---------------------------------------------------------------------------
extern "C" void kernel_launch(void* const* d_in, const int* in_sizes, int n_in,
                              void* d_out, int out_size)
{
    (void)in_sizes; (void)n_in; (void)out_size;
    const float* x  = (const float*)d_in[0];
    const float* Wq = (const float*)d_in[1];
    const float* bq = (const float*)d_in[2];
    const float* Wk = (const float*)d_in[3];
    const float* bk = (const float*)d_in[4];
    const float* Wv = (const float*)d_in[5];
    const float* bv = (const float*)d_in[6];
    const float* Wo = (const float*)d_in[7];
    const float* bo = (const float*)d_in[8];
    float* out = (float*)d_out;

    void *p;
    cudaGetSymbolAddress(&p, g_xh);  __half* xh = (__half*)p;
    cudaGetSymbolAddress(&p, g_xl);  __half* xl = (__half*)p;
    cudaGetSymbolAddress(&p, g_Qh);  __nv_bfloat16* Qh = (__nv_bfloat16*)p;
    cudaGetSymbolAddress(&p, g_Ql);  __nv_bfloat16* Ql = (__nv_bfloat16*)p;
    cudaGetSymbolAddress(&p, g_Kh);  __nv_bfloat16* Kh = (__nv_bfloat16*)p;
    cudaGetSymbolAddress(&p, g_Kl);  __nv_bfloat16* Kl = (__nv_bfloat16*)p;
    cudaGetSymbolAddress(&p, g_Vh);  __nv_bfloat16* Vh = (__nv_bfloat16*)p;
    cudaGetSymbolAddress(&p, g_Vl);  __nv_bfloat16* Vl = (__nv_bfloat16*)p;
    cudaGetSymbolAddress(&p, g_ah);  __half* ah = (__half*)p;
    cudaGetSymbolAddress(&p, g_al);  __half* al = (__half*)p;
    cudaGetSymbolAddress(&p, g_wh);  __half* wh = (__half*)p;

    const size_t WSZ = (size_t)EMBED * EMBED;
    const int GEMM_SMEM  = 2 * GSTG;       // 61440 B
    const int FLASH_SMEM = 10 * FT;        // 92160 B -> 2 CTAs/SM
    cudaFuncSetAttribute(gemm_mma<1>, cudaFuncAttributeMaxDynamicSharedMemorySize,
                         GEMM_SMEM);
    cudaFuncSetAttribute(gemm_mma<0>, cudaFuncAttributeMaxDynamicSharedMemorySize,
                         GEMM_SMEM);
    cudaFuncSetAttribute(flash_attn, cudaFuncAttributeMaxDynamicSharedMemorySize,
                         FLASH_SMEM);

    // 1) fp32 -> fp16 conversions (single merged launch)
    conv_all<<<dim3(32, 32, 8), dim3(32, 8)>>>(x, Wq, Wk, Wv, Wo, xh, xl, wh);

    // 2) fused QKV projection (fp16 2-term) -> bf16 hi/lo split outputs
    dim3 g1(EMBED / 128, NTOK / 128, 3);
    gemm_mma<1><<<g1, 256, GEMM_SMEM>>>(xh, xl,
                                        wh, wh + WSZ, wh + 2 * WSZ,
                                        bq, bk, bv, nullptr,
                                        Qh, Kh, Vh, Ql, Kl, Vl);

    // 3) tensor-core causal flash attention (frozen bf16x3 internals)
    dim3 g2(TSEQ / 64, NH, 2);
    flash_attn<<<g2, 128, FLASH_SMEM>>>(Qh, Ql, Kh, Kl, Vh, Vl, ah, al);

    // 4) output projection (fp16 2-term) -> fp32
    dim3 g3(EMBED / 128, NTOK / 128, 1);
    gemm_mma<0><<<g3, 256, GEMM_SMEM>>>(ah, al,
                                        wh + 3 * WSZ, wh + 3 * WSZ, wh + 3 * WSZ,
                                        bo, bo, bo, out,
                                        nullptr, nullptr, nullptr,
                                        nullptr, nullptr, nullptr);
}

// round 17
// speedup vs baseline: 1.4661x; 1.1790x over previous
#include <cuda_runtime.h>
#include <cuda_bf16.h>
#include <cuda_fp16.h>
#include <math.h>
#include <stdint.h>

// Problem constants
#define NTOK  4096      // B*T
#define TSEQ  2048
#define EMBED 1024
#define NH    16
#define HDIM  64

// ---------------------------------------------------------------------------
// Scratch (device globals: allocation-free per harness rules)
// ---------------------------------------------------------------------------
__device__ __half g_xh[(size_t)NTOK * EMBED];
__device__ __half g_xl[(size_t)NTOK * EMBED];
__device__ __half g_Qh[(size_t)NTOK * EMBED];
__device__ __half g_Ql[(size_t)NTOK * EMBED];
__device__ __half g_Kh[(size_t)NTOK * EMBED];   // hi only (2-term QK)
__device__ __half g_Vh[(size_t)NTOK * EMBED];   // hi only (2-term PV)
__device__ __half g_ah[(size_t)NTOK * EMBED];
__device__ __half g_al[(size_t)NTOK * EMBED];
__device__ __half g_wh[(size_t)4 * EMBED * EMBED];  // Wq^T,Wk^T,Wv^T,Wo^T fp16

// ---------------------------------------------------------------------------
// PTX helpers (compute_103-safe: ldmatrix + mma.sync + cp.async)
// ---------------------------------------------------------------------------
__device__ __forceinline__ uint32_t smem_u32(const void* p) {
    uint32_t a;
    asm("{ .reg .u64 t; cvta.to.shared.u64 t, %1; cvt.u32.u64 %0, t; }"
        : "=r"(a) : "l"(p));
    return a;
}

__device__ __forceinline__ void cp16(uint32_t dst, const void* src) {
    asm volatile("cp.async.cg.shared.global [%0], [%1], 16;"
                 :: "r"(dst), "l"(src));
}
#define CP_COMMIT() asm volatile("cp.async.commit_group;" ::: "memory")
#define CP_WAIT0()  asm volatile("cp.async.wait_group 0;" ::: "memory")
#define CP_WAIT1()  asm volatile("cp.async.wait_group 1;" ::: "memory")

__device__ __forceinline__ void ldsm_x4(uint32_t addr, uint32_t& r0, uint32_t& r1,
                                        uint32_t& r2, uint32_t& r3) {
    asm volatile("ldmatrix.sync.aligned.m8n8.x4.shared.b16 {%0,%1,%2,%3}, [%4];"
                 : "=r"(r0), "=r"(r1), "=r"(r2), "=r"(r3) : "r"(addr));
}

__device__ __forceinline__ void ldsm_x4_t(uint32_t addr, uint32_t& r0, uint32_t& r1,
                                          uint32_t& r2, uint32_t& r3) {
    asm volatile("ldmatrix.sync.aligned.m8n8.x4.trans.shared.b16 {%0,%1,%2,%3}, [%4];"
                 : "=r"(r0), "=r"(r1), "=r"(r2), "=r"(r3) : "r"(addr));
}

// fp16 MMA
__device__ __forceinline__ void mma16816h(float* d, const uint32_t* a,
                                          const uint32_t* b) {
    asm volatile(
        "mma.sync.aligned.m16n8k16.row.col.f32.f16.f16.f32 "
        "{%0,%1,%2,%3}, {%4,%5,%6,%7}, {%8,%9}, {%0,%1,%2,%3};"
        : "+f"(d[0]), "+f"(d[1]), "+f"(d[2]), "+f"(d[3])
        : "r"(a[0]), "r"(a[1]), "r"(a[2]), "r"(a[3]), "r"(b[0]), "r"(b[1]));
}

// fp32 -> (fp16 hi, fp16 lo) packed pair
__device__ __forceinline__ void split2h(float a, float b, uint32_t& hi, uint32_t& lo) {
    __half ha = __float2half_rn(a);
    __half hb = __float2half_rn(b);
    __half2 hp = __halves2half2(ha, hb);
    hi = *reinterpret_cast<uint32_t*>(&hp);
    __half2 lp = __floats2half2_rn(a - __half2float(ha),
                                   b - __half2float(hb));
    lo = *reinterpret_cast<uint32_t*>(&lp);
}

// Software exp2 on the FMA pipe (no MUFU). rel err ~2e-6.
__device__ __forceinline__ float fexp2(float x) {
    x = fmaxf(x, -125.0f);
    float t = __fadd_rn(x, 12582912.0f);
    int   k = __float_as_int(t) - 0x4B400000;
    float f = __fsub_rn(x, __fsub_rn(t, 12582912.0f));
    float p = 1.3333558146e-3f;
    p = fmaf(p, f, 9.6181291077e-3f);
    p = fmaf(p, f, 5.5504108664e-2f);
    p = fmaf(p, f, 2.4022650696e-1f);
    p = fmaf(p, f, 6.9314718056e-1f);
    p = fmaf(p, f, 1.0f);
    return p * __int_as_float((k + 127) << 23);
}

// ---------------------------------------------------------------------------
// Kernel 1 (merged conversions):
//   z = 0..3 : W [K,N] fp32 -> W^T [N,K] fp16 (hi only)
//   z = 4..7 : x slab (z-4)*1024 rows -> xh/xl fp16 2-level split
// ---------------------------------------------------------------------------
__global__ __launch_bounds__(256)
void conv_all(const float* __restrict__ x,
              const float* __restrict__ W0, const float* __restrict__ W1,
              const float* __restrict__ W2, const float* __restrict__ W3,
              __half* __restrict__ xh, __half* __restrict__ xl,
              __half* __restrict__ wh)
{
    __shared__ float tile[32][33];
    const int z = blockIdx.z;

    if (z >= 4) {
        const int c  = blockIdx.x * 32 + threadIdx.x;
        const int r0 = (z - 4) * 1024 + blockIdx.y * 32 + threadIdx.y;
#pragma unroll
        for (int j = 0; j < 32; j += 8) {
            const size_t idx = (size_t)(r0 + j) * EMBED + c;
            float v = x[idx];
            __half h = __float2half_rn(v);
            xh[idx] = h;
            xl[idx] = __float2half_rn(v - __half2float(h));
        }
        return;
    }

    const float* W = W0;
    if (z == 1) W = W1;
    else if (z == 2) W = W2;
    else if (z == 3) W = W3;

    const int xc = blockIdx.x * 32 + threadIdx.x;
    const int yc = blockIdx.y * 32 + threadIdx.y;
#pragma unroll
    for (int j = 0; j < 32; j += 8)
        tile[threadIdx.y + j][threadIdx.x] = W[(size_t)(yc + j) * EMBED + xc];
    __syncthreads();

    const int xo = blockIdx.y * 32 + threadIdx.x;
    const int yo = blockIdx.x * 32 + threadIdx.y;
    const size_t zo = (size_t)z * EMBED * EMBED;
#pragma unroll
    for (int j = 0; j < 32; j += 8)
        wh[zo + (size_t)(yo + j) * EMBED + xo] =
            __float2half_rn(tile[threadIdx.x][threadIdx.y + j]);
}

// ---------------------------------------------------------------------------
// Kernel 2: fp16 2-term GEMM (D = Ah*Bh + Al*Bh) + cp.async 2-stage pipeline.
//   SPLIT=1: fp16 hi (+lo iff Dl non-null) outputs;  SPLIT=0: fp32 output.
// ---------------------------------------------------------------------------
#define TSTR  40                     // padded k-stride (elems)
#define GT    (128 * TSTR * 2)       // tile bytes (10240)
#define GSTG  (3 * GT)               // stage bytes (30720)

__device__ __forceinline__ void cpa_tile(uint32_t sbase,
                                         const __half* __restrict__ g,
                                         int tid)
{
#pragma unroll
    for (int it = 0; it < 2; it++) {
        const int c   = tid + it * 256;
        const int r   = c >> 2;
        const int col = (c & 3) << 3;
        cp16(sbase + (uint32_t)(r * TSTR + col) * 2, g + (size_t)r * EMBED + col);
    }
}

template<int SPLIT>
__global__ __launch_bounds__(256, 2)
void gemm_mma(const __half* __restrict__ Ahi, const __half* __restrict__ Alo,
              const __half* __restrict__ Bh0, const __half* __restrict__ Bh1,
              const __half* __restrict__ Bh2,
              const float* __restrict__ c0, const float* __restrict__ c1,
              const float* __restrict__ c2,
              float* __restrict__ F0,
              __half* __restrict__ H0, __half* __restrict__ H1,
              __half* __restrict__ H2,
              __half* __restrict__ L0, __half* __restrict__ L1,
              __half* __restrict__ L2)
{
    extern __shared__ __align__(16) __half gsm[];
    const uint32_t sb = smem_u32(gsm);

    const __half* Bhi = Bh0;
    const float* bias = c0;
    __half* Dh = H0;
    __half* Dl = L0;
    if (blockIdx.z == 1)      { Bhi = Bh1; bias = c1; Dh = H1; Dl = L1; }
    else if (blockIdx.z == 2) { Bhi = Bh2; bias = c2; Dh = H2; Dl = L2; }

    const int tid    = threadIdx.x;
    const int lane   = tid & 31;
    const int wid    = tid >> 5;
    const int warp_m = wid >> 2;
    const int warp_n = wid & 3;
    const int bm     = blockIdx.y * 128;
    const int bn     = blockIdx.x * 128;

    const uint32_t aRow = warp_m * 64 + (lane & 15);
    const uint32_t aOff = aRow * (TSTR * 2) + ((lane >> 4) << 4);
    const uint32_t bg   = lane >> 3;
    const uint32_t bRow = warp_n * 32 + ((bg >> 1) << 3) + (lane & 7);
    const uint32_t bOff = bRow * (TSTR * 2) + ((bg & 1) << 4);

    float acc[4][4][4];
#pragma unroll
    for (int i = 0; i < 4; i++)
#pragma unroll
        for (int j = 0; j < 4; j++)
#pragma unroll
            for (int q = 0; q < 4; q++) acc[i][j][q] = 0.0f;

    const __half* gAh = Ahi + (size_t)bm * EMBED;
    const __half* gAl = Alo + (size_t)bm * EMBED;
    const __half* gBh = Bhi + (size_t)bn * EMBED;

    // prologue: prefetch stage 0
    {
        cpa_tile(sb,          gAh, tid);
        cpa_tile(sb + GT,     gAl, tid);
        cpa_tile(sb + 2 * GT, gBh, tid);
    }
    CP_COMMIT();

    for (int kb = 0; kb < EMBED / 32; kb++) {
        CP_WAIT0();
        __syncthreads();

        if (kb + 1 < EMBED / 32) {
            const int kc = (kb + 1) * 32;
            const uint32_t stB = sb + ((kb + 1) & 1) * GSTG;
            cpa_tile(stB,          gAh + kc, tid);
            cpa_tile(stB + GT,     gAl + kc, tid);
            cpa_tile(stB + 2 * GT, gBh + kc, tid);
            CP_COMMIT();
        }

        const uint32_t stB = sb + (kb & 1) * GSTG;
        const uint32_t aHb = stB + aOff;
        const uint32_t aLb = stB + GT + aOff;
        const uint32_t bHb = stB + 2 * GT + bOff;

#pragma unroll
        for (int ks = 0; ks < 2; ks++) {
            uint32_t ah[4][4], al[4][4], bh[4][2];
#pragma unroll
            for (int mi = 0; mi < 4; mi++) {
                const uint32_t d = mi * (16 * TSTR * 2) + ks * 32;
                ldsm_x4(aHb + d, ah[mi][0], ah[mi][1], ah[mi][2], ah[mi][3]);
                ldsm_x4(aLb + d, al[mi][0], al[mi][1], al[mi][2], al[mi][3]);
            }
#pragma unroll
            for (int np = 0; np < 2; np++) {
                const uint32_t d = np * (16 * TSTR * 2) + ks * 32;
                ldsm_x4(bHb + d, bh[np*2][0], bh[np*2][1], bh[np*2+1][0], bh[np*2+1][1]);
            }
#pragma unroll
            for (int mi = 0; mi < 4; mi++)
#pragma unroll
                for (int ni = 0; ni < 4; ni++)
                    mma16816h(acc[mi][ni], ah[mi], bh[ni]);
#pragma unroll
            for (int mi = 0; mi < 4; mi++)
#pragma unroll
                for (int ni = 0; ni < 4; ni++)
                    mma16816h(acc[mi][ni], al[mi], bh[ni]);
        }
    }

#pragma unroll
    for (int ni = 0; ni < 4; ni++) {
        const int col = bn + warp_n * 32 + ni * 8 + ((lane & 3) << 1);
        const float2 bv = *(const float2*)(bias + col);
#pragma unroll
        for (int mi = 0; mi < 4; mi++) {
            const int row = bm + warp_m * 64 + mi * 16 + (lane >> 2);
            const float a0 = acc[mi][ni][0] + bv.x;
            const float a1 = acc[mi][ni][1] + bv.y;
            const float a2 = acc[mi][ni][2] + bv.x;
            const float a3 = acc[mi][ni][3] + bv.y;
            if (SPLIT) {
                uint32_t h01, l01, h23, l23;
                split2h(a0, a1, h01, l01);
                split2h(a2, a3, h23, l23);
                *(uint32_t*)(Dh + (size_t)row * EMBED + col)       = h01;
                *(uint32_t*)(Dh + (size_t)(row + 8) * EMBED + col) = h23;
                if (Dl) {
                    *(uint32_t*)(Dl + (size_t)row * EMBED + col)       = l01;
                    *(uint32_t*)(Dl + (size_t)(row + 8) * EMBED + col) = l23;
                }
            } else {
                float2 o0, o1;
                o0.x = a0; o0.y = a1; o1.x = a2; o1.y = a3;
                *(float2*)(F0 + (size_t)row * EMBED + col)       = o0;
                *(float2*)(F0 + (size_t)(row + 8) * EMBED + col) = o1;
            }
        }
    }
}

// ---------------------------------------------------------------------------
// Kernel 3: tensor-core flash attention (causal), fp16 2-term numerics.
//   QK = Qh*Kh + Ql*Kh  (K fp16 hi-only); PV = Ph*Vh + Pl*Vh (V fp16 hi-only).
//   64x64 tiles, K/V double-buffered cp.async, 2 CTAs/SM.
//   smem: Qh | Ql | K0 | K1 | V0 | V1 = 6 tiles = 55296 B.
// ---------------------------------------------------------------------------
#define FSTR 72                  // padded row stride (fp16)
#define FT   (64 * FSTR * 2)     // tile bytes (9216)

__device__ __forceinline__ void cpa64(uint32_t sbase,
                                      const __half* __restrict__ g,
                                      int tid)
{
#pragma unroll
    for (int it = 0; it < 4; it++) {
        const int idx = tid + it * 128;
        const int r = idx >> 3, c = (idx & 7) << 3;
        cp16(sbase + (uint32_t)(r * FSTR + c) * 2, g + (size_t)r * EMBED + c);
    }
}

__global__ __launch_bounds__(128, 2)
void flash_attn(const __half* __restrict__ Qh, const __half* __restrict__ Ql,
                const __half* __restrict__ Kh, const __half* __restrict__ Vh,
                __half* __restrict__ Oh, __half* __restrict__ Ol)
{
    extern __shared__ __align__(16) __half sm[];
    const uint32_t sb = smem_u32(sm);
    // layout: Qh | Ql | K0 | K1 | V0 | V1

    const int tid  = threadIdx.x;
    const int lane = tid & 31;
    const int wid  = tid >> 5;
    const int qt   = gridDim.x - 1 - blockIdx.x;   // heavy tiles first
    const int h    = blockIdx.y;
    const int b    = blockIdx.z;

    const size_t base = (size_t)b * TSEQ * EMBED + (size_t)h * HDIM;
    const int q0 = qt * 64;

    // ---- prefetch K/V tile j=0 into stage 0 ----
    cpa64(sb + 2 * FT, Kh + base, tid);
    cpa64(sb + 4 * FT, Vh + base, tid);
    CP_COMMIT();

    // ---- load Q tile (hi/lo) and cache A-frags in registers ----
    {
        const __half* gq  = Qh + base + (size_t)q0 * EMBED;
        const __half* gql = Ql + base + (size_t)q0 * EMBED;
        __half* sQh = sm;
        __half* sQl = sm + 64 * FSTR;
#pragma unroll
        for (int it = 0; it < 4; it++) {
            const int idx = tid + it * 128;
            const int r = idx >> 3, c = (idx & 7) << 3;
            *(uint4*)(sQh + r * FSTR + c) = *(const uint4*)(gq  + (size_t)r * EMBED + c);
            *(uint4*)(sQl + r * FSTR + c) = *(const uint4*)(gql + (size_t)r * EMBED + c);
        }
    }
    __syncthreads();

    uint32_t qfh[4][4], qfl[4][4];
    {
        const uint32_t aOff = ((wid * 16 + (lane & 15)) * FSTR + ((lane >> 4) << 3)) * 2;
        const uint32_t ah = sb + aOff;
        const uint32_t al = sb + FT + aOff;
#pragma unroll
        for (int kf = 0; kf < 4; kf++) {
            ldsm_x4(ah + kf * 32, qfh[kf][0], qfh[kf][1], qfh[kf][2], qfh[kf][3]);
            ldsm_x4(al + kf * 32, qfl[kf][0], qfl[kf][1], qfl[kf][2], qfl[kf][3]);
        }
    }

    // B-frag lane addressing (K normal, V trans)
    const uint32_t bg = lane >> 3;
    const uint32_t kOff = ((((bg >> 1) << 3) + (lane & 7)) * FSTR + ((bg & 1) << 3)) * 2;
    const uint32_t vOff = ((((bg & 1) << 3) + (lane & 7)) * FSTR + ((bg >> 1) << 3)) * 2;

    float ofr[8][4];
#pragma unroll
    for (int nf = 0; nf < 8; nf++)
#pragma unroll
        for (int q = 0; q < 4; q++) ofr[nf][q] = 0.0f;
    float m0 = -1e30f, m1 = -1e30f, l0 = 0.0f, l1 = 0.0f;

    const float SC = 0.18033688011112042f;   // 0.125 * log2(e)
    const int r0loc = wid * 16 + (lane >> 2);

    for (int j = 0; j <= qt; j++) {
        // prefetch next K/V tile into the other stage
        if (j < qt) {
            const size_t koff = base + (size_t)((j + 1) * 64) * EMBED;
            const int s = (j + 1) & 1;
            cpa64(sb + (2 + s) * FT, Kh + koff, tid);
            cpa64(sb + (4 + s) * FT, Vh + koff, tid);
        }
        CP_COMMIT();
        CP_WAIT1();
        __syncthreads();

        const int s = j & 1;
        const uint32_t kB = sb + (2 + s) * FT;
        const uint32_t vB = sb + (4 + s) * FT;

        // ---- S = Q K^T (fp16 2-term) ----
        float sfr[8][4];
#pragma unroll
        for (int nf = 0; nf < 8; nf++)
#pragma unroll
            for (int q = 0; q < 4; q++) sfr[nf][q] = 0.0f;

        const uint32_t kh0 = kB + kOff;
#pragma unroll
        for (int ks = 0; ks < 4; ks++) {
            uint32_t bh[16];
#pragma unroll
            for (int nb = 0; nb < 4; nb++) {
                const uint32_t d = nb * (16 * FSTR * 2) + ks * 32;
                ldsm_x4(kh0 + d, bh[nb*4+0], bh[nb*4+1], bh[nb*4+2], bh[nb*4+3]);
            }
#pragma unroll
            for (int nf = 0; nf < 8; nf++)
                mma16816h(sfr[nf], qfh[ks], &bh[nf*2]);
#pragma unroll
            for (int nf = 0; nf < 8; nf++)
                mma16816h(sfr[nf], qfl[ks], &bh[nf*2]);
        }

        // ---- scale + causal mask ----
        if (j == qt) {
#pragma unroll
            for (int nf = 0; nf < 8; nf++)
#pragma unroll
                for (int q = 0; q < 4; q++) {
                    const int col = nf * 8 + ((lane & 3) << 1) + (q & 1);
                    const int row = r0loc + ((q >> 1) << 3);
                    sfr[nf][q] = (col <= row) ? sfr[nf][q] * SC : -1e30f;
                }
        } else {
#pragma unroll
            for (int nf = 0; nf < 8; nf++)
#pragma unroll
                for (int q = 0; q < 4; q++) sfr[nf][q] *= SC;
        }

        // ---- online softmax (base-2, FFMA-pipe exp) ----
        float mx0 = -1e30f, mx1 = -1e30f;
#pragma unroll
        for (int nf = 0; nf < 8; nf++) {
            mx0 = fmaxf(mx0, fmaxf(sfr[nf][0], sfr[nf][1]));
            mx1 = fmaxf(mx1, fmaxf(sfr[nf][2], sfr[nf][3]));
        }
        mx0 = fmaxf(mx0, __shfl_xor_sync(0xffffffffu, mx0, 1));
        mx0 = fmaxf(mx0, __shfl_xor_sync(0xffffffffu, mx0, 2));
        mx1 = fmaxf(mx1, __shfl_xor_sync(0xffffffffu, mx1, 1));
        mx1 = fmaxf(mx1, __shfl_xor_sync(0xffffffffu, mx1, 2));

        const float mn0 = fmaxf(m0, mx0);
        const float mn1 = fmaxf(m1, mx1);
        const float a0 = fexp2(m0 - mn0);
        const float a1 = fexp2(m1 - mn1);
        m0 = mn0; m1 = mn1;

        float rs0 = 0.0f, rs1 = 0.0f;
#pragma unroll
        for (int nf = 0; nf < 8; nf++) {
            sfr[nf][0] = fexp2(sfr[nf][0] - mn0);
            sfr[nf][1] = fexp2(sfr[nf][1] - mn0);
            sfr[nf][2] = fexp2(sfr[nf][2] - mn1);
            sfr[nf][3] = fexp2(sfr[nf][3] - mn1);
            rs0 += sfr[nf][0] + sfr[nf][1];
            rs1 += sfr[nf][2] + sfr[nf][3];
        }
        rs0 += __shfl_xor_sync(0xffffffffu, rs0, 1);
        rs0 += __shfl_xor_sync(0xffffffffu, rs0, 2);
        rs1 += __shfl_xor_sync(0xffffffffu, rs1, 1);
        rs1 += __shfl_xor_sync(0xffffffffu, rs1, 2);
        l0 = l0 * a0 + rs0;
        l1 = l1 * a1 + rs1;

#pragma unroll
        for (int nf = 0; nf < 8; nf++) {
            ofr[nf][0] *= a0; ofr[nf][1] *= a0;
            ofr[nf][2] *= a1; ofr[nf][3] *= a1;
        }

        // ---- pack P into A-frags (fp16 hi/lo) ----
        uint32_t pah[4][4], pal[4][4];
#pragma unroll
        for (int kf = 0; kf < 4; kf++) {
            split2h(sfr[2*kf][0],   sfr[2*kf][1],   pah[kf][0], pal[kf][0]);
            split2h(sfr[2*kf][2],   sfr[2*kf][3],   pah[kf][1], pal[kf][1]);
            split2h(sfr[2*kf+1][0], sfr[2*kf+1][1], pah[kf][2], pal[kf][2]);
            split2h(sfr[2*kf+1][2], sfr[2*kf+1][3], pah[kf][3], pal[kf][3]);
        }

        // ---- O += P V (fp16 2-term, V via ldmatrix.trans) ----
        const uint32_t vh0 = vB + vOff;
#pragma unroll
        for (int kf = 0; kf < 4; kf++) {
            uint32_t vh[16];
#pragma unroll
            for (int nb = 0; nb < 4; nb++) {
                const uint32_t d = kf * (16 * FSTR * 2) + nb * 32;
                ldsm_x4_t(vh0 + d, vh[nb*4+0], vh[nb*4+1], vh[nb*4+2], vh[nb*4+3]);
            }
#pragma unroll
            for (int nf = 0; nf < 8; nf++)
                mma16816h(ofr[nf], pah[kf], &vh[nf*2]);
#pragma unroll
            for (int nf = 0; nf < 8; nf++)
                mma16816h(ofr[nf], pal[kf], &vh[nf*2]);
        }
        __syncthreads();
    }

    // ---- finalize: O /= l, write fp16 hi/lo split ----
    const float i0 = 1.0f / l0;
    const float i1 = 1.0f / l1;
    const int row0 = q0 + r0loc;
#pragma unroll
    for (int nf = 0; nf < 8; nf++) {
        const int col = nf * 8 + ((lane & 3) << 1);
        uint32_t h01, l01, h23, l23;
        split2h(ofr[nf][0] * i0, ofr[nf][1] * i0, h01, l01);
        split2h(ofr[nf][2] * i1, ofr[nf][3] * i1, h23, l23);
        const size_t o0 = base + (size_t)row0 * EMBED + col;
        const size_t o1 = base + (size_t)(row0 + 8) * EMBED + col;
        *(uint32_t*)(Oh + o0) = h01;
        *(uint32_t*)(Ol + o0) = l01;
        *(uint32_t*)(Oh + o1) = h23;
        *(uint32_t*)(Ol + o1) = l23;
    }
}

// ---------------------------------------------------------------------------
// Launch
// ---------------------------------------------------------------------------
extern "C" void kernel_launch(void* const* d_in, const int* in_sizes, int n_in,
                              void* d_out, int out_size)
{
    (void)in_sizes; (void)n_in; (void)out_size;
    const float* x  = (const float*)d_in[0];
    const float* Wq = (const float*)d_in[1];
    const float* bq = (const float*)d_in[2];
    const float* Wk = (const float*)d_in[3];
    const float* bk = (const float*)d_in[4];
    const float* Wv = (const float*)d_in[5];
    const float* bv = (const float*)d_in[6];
    const float* Wo = (const float*)d_in[7];
    const float* bo = (const float*)d_in[8];
    float* out = (float*)d_out;

    void *p;
    cudaGetSymbolAddress(&p, g_xh);  __half* xh = (__half*)p;
    cudaGetSymbolAddress(&p, g_xl);  __half* xl = (__half*)p;
    cudaGetSymbolAddress(&p, g_Qh);  __half* Qh = (__half*)p;
    cudaGetSymbolAddress(&p, g_Ql);  __half* Ql = (__half*)p;
    cudaGetSymbolAddress(&p, g_Kh);  __half* Kh = (__half*)p;
    cudaGetSymbolAddress(&p, g_Vh);  __half* Vh = (__half*)p;
    cudaGetSymbolAddress(&p, g_ah);  __half* ah = (__half*)p;
    cudaGetSymbolAddress(&p, g_al);  __half* al = (__half*)p;
    cudaGetSymbolAddress(&p, g_wh);  __half* wh = (__half*)p;

    const size_t WSZ = (size_t)EMBED * EMBED;
    const int GEMM_SMEM  = 2 * GSTG;       // 61440 B
    const int FLASH_SMEM = 6 * FT;         // 55296 B
    cudaFuncSetAttribute(gemm_mma<1>, cudaFuncAttributeMaxDynamicSharedMemorySize,
                         GEMM_SMEM);
    cudaFuncSetAttribute(gemm_mma<0>, cudaFuncAttributeMaxDynamicSharedMemorySize,
                         GEMM_SMEM);
    cudaFuncSetAttribute(flash_attn, cudaFuncAttributeMaxDynamicSharedMemorySize,
                         FLASH_SMEM);

    // 1) fp32 -> fp16 conversions (single merged launch)
    conv_all<<<dim3(32, 32, 8), dim3(32, 8)>>>(x, Wq, Wk, Wv, Wo, xh, xl, wh);

    // 2) fused QKV projection (fp16 2-term):
    //    Q -> hi+lo; K,V -> hi only (2-term flash drops their lo terms)
    dim3 g1(EMBED / 128, NTOK / 128, 3);
    gemm_mma<1><<<g1, 256, GEMM_SMEM>>>(xh, xl,
                                        wh, wh + WSZ, wh + 2 * WSZ,
                                        bq, bk, bv, nullptr,
                                        Qh, Kh, Vh,
                                        Ql, nullptr, nullptr);

    // 3) tensor-core causal flash attention (fp16 2-term)
    dim3 g2(TSEQ / 64, NH, 2);
    flash_attn<<<g2, 128, FLASH_SMEM>>>(Qh, Ql, Kh, Vh, ah, al);

    // 4) output projection (fp16 2-term) -> fp32
    dim3 g3(EMBED / 128, NTOK / 128, 1);
    gemm_mma<0><<<g3, 256, GEMM_SMEM>>>(ah, al,
                                        wh + 3 * WSZ, wh + 3 * WSZ, wh + 3 * WSZ,
                                        bo, bo, bo, out,
                                        nullptr, nullptr, nullptr,
                                        nullptr, nullptr, nullptr);
}